// round 14
// baseline (speedup 1.0000x reference)
#include <cuda_runtime.h>
#include <math.h>

#define BB 2
#define LL 1024
#define DM 768
#define NH 12
#define DKK 64
#define FFD 3072
#define PH 32
#define ROWS (BB*LL)

// ---------------- scratch ----------------
__device__ float g_Q[BB*NH*LL*DKK];
__device__ float g_K[BB*NH*LL*DKK];
__device__ float g_V[BB*NH*LL*DKK];
__device__ float g_S[(size_t)BB*NH*LL*LL];
__device__ float g_O[BB*LL*DM];
__device__ float g_Xres[BB*LL*DM];
__device__ float g_X1[BB*LL*DM];
__device__ float g_H1[BB*LL*FFD];

// ---------------- helpers ----------------
__device__ __forceinline__ unsigned tf32u(float x) {
    unsigned u;
    asm("cvt.rna.tf32.f32 %0, %1;" : "=r"(u) : "f"(x));
    return u;
}
__device__ __forceinline__ float tf32f(float x) { return __uint_as_float(tf32u(x)); }

// mma consumes raw fp32 bits as tf32 (HW truncates low mantissa bits)
__device__ __forceinline__ void mma_tf32(float* c, const unsigned* a, const unsigned* b) {
    asm volatile(
        "mma.sync.aligned.m16n8k8.row.col.f32.tf32.tf32.f32 "
        "{%0,%1,%2,%3}, {%4,%5,%6,%7}, {%8,%9}, {%0,%1,%2,%3};"
        : "+f"(c[0]), "+f"(c[1]), "+f"(c[2]), "+f"(c[3])
        : "r"(a[0]), "r"(a[1]), "r"(a[2]), "r"(a[3]), "r"(b[0]), "r"(b[1]));
}

__device__ __forceinline__ void ldmatrix_x4(unsigned& r0, unsigned& r1,
                                            unsigned& r2, unsigned& r3, unsigned addr) {
    asm volatile("ldmatrix.sync.aligned.m8n8.x4.shared.b16 {%0,%1,%2,%3}, [%4];"
        : "=r"(r0), "=r"(r1), "=r"(r2), "=r"(r3) : "r"(addr));
}

__device__ __forceinline__ unsigned smem_u32(const void* p) {
    return (unsigned)__cvta_generic_to_shared(p);
}

__device__ __forceinline__ void cp16(float* dst_smem, const float* src) {
    unsigned d = (unsigned)__cvta_generic_to_shared(dst_smem);
    asm volatile("cp.async.cg.shared.global [%0], [%1], 16;" :: "r"(d), "l"(src));
}
__device__ __forceinline__ void cp_commit() { asm volatile("cp.async.commit_group;"); }
template<int N> __device__ __forceinline__ void cp_wait() {
    asm volatile("cp.async.wait_group %0;" :: "n"(N));
}

// ---------------- tensor-core GEMM body: BK=32, multi-stage cp.async, ldmatrix A ----
// EPI 1: relu(+bias)  2: +bias +R residual  3: fused QKV scatter
// 8 warps = 2(m) x 4(n). Warp tile (BM/2) x (BN/4).
template<int EPI, int BM, int BN>
__device__ __forceinline__ void tgemm_body(
    int bxi, int byi,
    const float* __restrict__ A, int lda,
    const float* __restrict__ B, int ldb,
    const float* __restrict__ bias,
    const float* __restrict__ Rres,
    float* __restrict__ C, int ldc,
    int K,
    const float* __restrict__ B1, const float* __restrict__ B2,
    const float* __restrict__ bias1, const float* __restrict__ bias2,
    float* __restrict__ C1, float* __restrict__ C2,
    float* dynsm)
{
    constexpr int MI  = BM / 32;
    constexpr int NT  = BN / 32;
    constexpr int WNS = BN / 4;
    constexpr int ST  = (BM == 64 && BN == 64) ? 4 : 3;
    constexpr int AP  = 36;
    constexpr int BP  = BN + 8;
    constexpr int ASZ = BM * AP;
    constexpr int BSZ = 32 * BP;
    float* As = dynsm;
    float* Bs = dynsm + ST * ASZ;

    const int tid = threadIdx.x;
    const int lane = tid & 31, w = tid >> 5;
    const int wm = w & 1, wn = w >> 1;
    const int g = lane >> 2, t4 = lane & 3;
    int bx = bxi;
    const int m0 = byi * BM;

    const float* Ap = A;
    const float* Bp = B; const float* biasp = bias; float* Cp = C;
    if (EPI == 3) {
        int sel = bx / 6; bx -= sel * 6;
        Bp    = sel == 0 ? B    : (sel == 1 ? B1    : B2);
        biasp = sel == 0 ? bias : (sel == 1 ? bias1 : bias2);
        Cp    = sel == 0 ? C    : (sel == 1 ? C1    : C2);
    }
    const int n0 = bx * BN;

    float acc[MI][NT][4];
    #pragma unroll
    for (int i = 0; i < MI; i++)
        #pragma unroll
        for (int j = 0; j < NT; j++)
            #pragma unroll
            for (int q = 0; q < 4; q++) acc[i][j][q] = 0.f;

    auto loadA = [&](int kt, int st) {
        #pragma unroll
        for (int i = 0; i < BM / 32; i++) {
            int idx = tid + i * 256;
            int m = idx >> 3, k4 = (idx & 7) << 2;
            cp16(&As[st * ASZ + m * AP + k4], Ap + (size_t)(m0 + m) * lda + kt + k4);
        }
    };
    auto loadB = [&](int kt, int st) {
        if (BN == 128) {
            #pragma unroll
            for (int i = 0; i < 4; i++) {
                int idx = tid + i * 256;
                int k = idx >> 5, n4 = (idx & 31) << 2;
                cp16(&Bs[st * BSZ + k * BP + n4], Bp + (size_t)(kt + k) * ldb + n0 + n4);
            }
        } else {
            #pragma unroll
            for (int i = 0; i < 2; i++) {
                int idx = tid + i * 256;
                int k = idx >> 4, n4 = (idx & 15) << 2;
                cp16(&Bs[st * BSZ + k * BP + n4], Bp + (size_t)(kt + k) * ldb + n0 + n4);
            }
        }
    };
    const int lmRow = lane & 15;
    const int lmCol = (lane >> 4) << 2;
    auto ldA = [&](int st, int kk, unsigned (&aF)[MI][4]) {
        #pragma unroll
        for (int i = 0; i < MI; i++) {
            int mb0 = wm * (MI * 16) + i * 16;
            unsigned addr = smem_u32(
                &As[st * ASZ + (mb0 + lmRow) * AP + kk * 8 + lmCol]);
            ldmatrix_x4(aF[i][0], aF[i][1], aF[i][2], aF[i][3], addr);
        }
    };
    auto ldB = [&](int st, int kk, unsigned (&bF)[NT][2]) {
        const int kc = kk * 8 + t4;
        #pragma unroll
        for (int j = 0; j < NT; j++) {
            int nb = wn * WNS + j * 8 + g;
            bF[j][0] = __float_as_uint(Bs[st * BSZ + kc * BP + nb]);
            bF[j][1] = __float_as_uint(Bs[st * BSZ + (kc + 4) * BP + nb]);
        }
    };
    auto compute = [&](int st) {
        unsigned aF[MI][4];
        unsigned bF[2][NT][2];
        ldB(st, 0, bF[0]);
        #pragma unroll
        for (int kk = 0; kk < 4; kk++) {
            const int cb = kk & 1;
            ldA(st, kk, aF);
            if (kk < 3) ldB(st, kk + 1, bF[cb ^ 1]);
            #pragma unroll
            for (int i = 0; i < MI; i++)
                #pragma unroll
                for (int j = 0; j < NT; j++)
                    mma_tf32(acc[i][j], aF[i], bF[cb][j]);
        }
    };

    const int nt = K >> 5;
    loadA(0, 0); loadB(0, 0); cp_commit();
    if (nt > 1) { loadA(32, 1); loadB(32, 1); cp_commit(); }
    if (ST == 4 && nt > 2) { loadA(64, 2); loadB(64, 2); cp_commit(); }
    for (int t = 0; t < nt; t++) {
        if (t + ST - 1 < nt)                 cp_wait<ST - 2>();
        else if (ST == 4 && t + 2 < nt)      cp_wait<1>();
        else                                 cp_wait<0>();
        __syncthreads();
        compute(t % ST);
        if (t + ST - 1 < nt) {
            int st = (t + ST - 1) % ST;
            loadA((t + ST - 1) << 5, st);
            loadB((t + ST - 1) << 5, st);
            cp_commit();
        }
    }

    auto epi = [&](int row, int col, float2 v) {
        float2 bb = *(const float2*)(biasp + col);
        v.x += bb.x; v.y += bb.y;
        if (EPI == 1) { v.x = fmaxf(v.x, 0.f); v.y = fmaxf(v.y, 0.f); }
        if (EPI == 2) {
            float2 r = *(const float2*)(Rres + (size_t)row * ldc + col);
            v.x += r.x; v.y += r.y;
        }
        if (EPI == 3) {
            int h = col >> 6, d = col & 63;
            float* dst = Cp + ((((size_t)(row >> 10) * NH + h) * LL + (row & 1023)) * DKK + d);
            *(float2*)dst = v;
            return;
        }
        *(float2*)(Cp + (size_t)row * ldc + col) = v;
    };

    #pragma unroll
    for (int i = 0; i < MI; i++) {
        int r0 = m0 + wm * (MI * 16) + i * 16 + g;
        #pragma unroll
        for (int j = 0; j < NT; j++) {
            int col = n0 + wn * WNS + j * 8 + t4 * 2;
            epi(r0,     col, make_float2(acc[i][j][0], acc[i][j][1]));
            epi(r0 + 8, col, make_float2(acc[i][j][2], acc[i][j][3]));
        }
    }
}

#define TG_SMEM(BM, BN) ((((BM) == 64 && (BN) == 64) ? 4 : 3) * ((BM) * 36 + 32 * ((BN) + 8)) * 4)

template<int EPI, int BM, int BN>
__global__ __launch_bounds__(256, (BM == 64 && BN == 64) ? 3 : 2) void tgemm(
    const float* __restrict__ A, int lda,
    const float* __restrict__ B, int ldb,
    const float* __restrict__ bias,
    const float* __restrict__ Rres,
    float* __restrict__ C, int ldc,
    int K,
    const float* __restrict__ B1, const float* __restrict__ B2,
    const float* __restrict__ bias1, const float* __restrict__ bias2,
    float* __restrict__ C1, float* __restrict__ C2)
{
    extern __shared__ float dynsm[];
    tgemm_body<EPI, BM, BN>(blockIdx.x, blockIdx.y, A, lda, B, ldb, bias, Rres,
                            C, ldc, K, B1, B2, bias1, bias2, C1, C2, dynsm);
}

// ---------------- posbias body: layer-1 scalar, layer-2 via tf32 mma ----------------
__device__ __forceinline__ void posbias_body(
    int kx, int qy, int b,
    const float* __restrict__ sx, const float* __restrict__ sy,
    const float* __restrict__ P1, const float* __restrict__ pb1,
    const float* __restrict__ P2, const float* __restrict__ pb2,
    float* __restrict__ S, float* dynsm)
{
    constexpr int HSTR = 260;
    constexpr int PSTR = 20;
    float* Hs   = dynsm;
    float* Ps   = Hs + 16 * HSTR * 2;
    float* sP1  = Ps + 16 * PSTR * 2;
    float* sPb1 = sP1 + 64;
    float* sPb2 = sPb1 + 32;
    float* qx   = sPb2 + 16;
    float* qy_  = qx + 16;
    float* kxp  = qy_ + 16;
    float* kyp  = kxp + 16;

    const int q0 = qy * 16, k0 = kx * 16;
    const int tid = threadIdx.x;
    const int lane = tid & 31, w = tid >> 5;
    const int g = lane >> 2, t4 = lane & 3;

    if (tid < 64) sP1[tid] = P1[tid];
    if (tid < 32) sPb1[tid] = pb1[tid];
    if (tid < 16) {
        sPb2[tid] = tid < NH ? pb2[tid] : 0.f;
        qx[tid]  = sx[b*LL + q0 + tid];
        qy_[tid] = sy[b*LL + q0 + tid];
        kxp[tid] = sx[b*LL + k0 + tid];
        kyp[tid] = sy[b*LL + k0 + tid];
    }
    #pragma unroll
    for (int ii = 0; ii < 2; ii++) {
        int v = tid + ii * 256;
        int n = v & 15, k = v >> 4;
        float val = (n < NH) ? P2[k * NH + n] : 0.f;
        int kk = k >> 3, hh = (k >> 2) & 1, cc = k & 3;
        Ps[((kk * 4 + cc) * PSTR + n) * 2 + hh] = val;
    }
    __syncthreads();

    {
        int qq = tid >> 4, kq = tid & 15;
        float rx = fminf(fmaxf(qx[qq] - kxp[kq], -1000.f), 1000.f) * 0.001f;
        float ry = fminf(fmaxf(qy_[qq] - kyp[kq], -1000.f), 1000.f) * 0.001f;
        #pragma unroll
        for (int kk = 0; kk < 4; kk++)
            #pragma unroll
            for (int cc = 0; cc < 4; cc++) {
                int j0 = kk * 8 + cc, j1 = j0 + 4;
                float h0 = fmaxf(fmaf(rx, sP1[j0], fmaf(ry, sP1[32+j0], sPb1[j0])), 0.f);
                float h1 = fmaxf(fmaf(rx, sP1[j1], fmaf(ry, sP1[32+j1], sPb1[j1])), 0.f);
                *(float2*)(&Hs[((kk * 4 + cc) * HSTR + tid) * 2]) = make_float2(h0, h1);
            }
    }
    __syncthreads();

    float acc[2][2][4];
    #pragma unroll
    for (int i = 0; i < 2; i++)
        #pragma unroll
        for (int j = 0; j < 2; j++)
            #pragma unroll
            for (int q = 0; q < 4; q++) acc[i][j][q] = 0.f;

    #pragma unroll
    for (int ks = 0; ks < 4; ks++) {
        unsigned aF[2][4];
        #pragma unroll
        for (int i = 0; i < 2; i++) {
            int mb = (w * 2 + i) * 16 + g;
            float2 lo = *(const float2*)(&Hs[((ks * 4 + t4) * HSTR + mb) * 2]);
            float2 hi = *(const float2*)(&Hs[((ks * 4 + t4) * HSTR + mb + 8) * 2]);
            aF[i][0] = __float_as_uint(lo.x); aF[i][1] = __float_as_uint(hi.x);
            aF[i][2] = __float_as_uint(lo.y); aF[i][3] = __float_as_uint(hi.y);
        }
        unsigned bF[2][2];
        #pragma unroll
        for (int j = 0; j < 2; j++) {
            float2 bb = *(const float2*)(&Ps[((ks * 4 + t4) * PSTR + j * 8 + g) * 2]);
            bF[j][0] = __float_as_uint(bb.x); bF[j][1] = __float_as_uint(bb.y);
        }
        #pragma unroll
        for (int i = 0; i < 2; i++)
            #pragma unroll
            for (int j = 0; j < 2; j++)
                mma_tf32(acc[i][j], aF[i], bF[j]);
    }

    #pragma unroll
    for (int i = 0; i < 2; i++) {
        int p0 = (w * 2 + i) * 16 + g;
        int p1 = p0 + 8;
        int q_0 = q0 + (p0 >> 4), k_0 = k0 + (p0 & 15);
        int q_1 = q0 + (p1 >> 4), k_1 = k0 + (p1 & 15);
        #pragma unroll
        for (int j = 0; j < 2; j++) {
            int c0 = j * 8 + t4 * 2, c1 = c0 + 1;
            if (c0 < NH) {
                S[((size_t)(b*NH + c0) * LL + q_0) * LL + k_0] = acc[i][j][0] + sPb2[c0];
                S[((size_t)(b*NH + c0) * LL + q_1) * LL + k_1] = acc[i][j][2] + sPb2[c0];
            }
            if (c1 < NH) {
                S[((size_t)(b*NH + c1) * LL + q_0) * LL + k_0] = acc[i][j][1] + sPb2[c1];
                S[((size_t)(b*NH + c1) * LL + q_1) * LL + k_1] = acc[i][j][3] + sPb2[c1];
            }
        }
    }
}

// ---------------- fused posbias + QKV (heterogeneous grid) ----------------
#define QKV_BLOCKS 288
#define PBQKV_GRID (QKV_BLOCKS + 64*64*BB)

__global__ __launch_bounds__(256, 2) void pbqkv_kernel(
    const float* __restrict__ src,
    const float* __restrict__ Wq, const float* __restrict__ bq,
    const float* __restrict__ Wk, const float* __restrict__ bk,
    const float* __restrict__ Wv, const float* __restrict__ bv,
    float* __restrict__ Q, float* __restrict__ Kq, float* __restrict__ V,
    const float* __restrict__ sx, const float* __restrict__ sy,
    const float* __restrict__ P1, const float* __restrict__ pb1,
    const float* __restrict__ P2, const float* __restrict__ pb2,
    float* __restrict__ S)
{
    extern __shared__ float dynsm[];
    const int bid = blockIdx.x;
    if (bid < QKV_BLOCKS) {
        tgemm_body<3, 128, 128>(bid % 18, bid / 18,
            src, DM, Wq, DM, bq, nullptr, Q, 0, DM,
            Wk, Wv, bk, bv, Kq, V, dynsm);
    } else {
        int p = bid - QKV_BLOCKS;
        posbias_body(p & 63, (p >> 6) & 63, p >> 12,
                     sx, sy, P1, pb1, P2, pb2, S, dynsm);
    }
}

// ---------------- flash64: QK^T + bias + online softmax + PV -----------------
#define FQSTR 68
struct Flash64Smem {
    float Qs[32*FQSTR*2];
    float Ss[32*FQSTR*2];
    float Ks[64*FQSTR];
    float Vs[64*FQSTR];
    float rowScale[64];
    float rowInv[64];
};
#define FL64_SMEM_BYTES sizeof(Flash64Smem)

__global__ __launch_bounds__(256, 3) void flash64_kernel(
    const float* __restrict__ S, const float* __restrict__ Q,
    const float* __restrict__ K, const float* __restrict__ V,
    float* __restrict__ O)
{
    extern __shared__ char smraw[];
    Flash64Smem& sm = *reinterpret_cast<Flash64Smem*>(smraw);

    const int tid = threadIdx.x;
    const int lane = tid & 31, w = tid >> 5;
    const int wm = w & 1, wn = w >> 1;
    const int g = lane >> 2, t4 = lane & 3;
    const int bh = blockIdx.y, b = bh / NH, h = bh % NH;
    const int q0 = blockIdx.x * 64;

    const float* Qp = Q + ((size_t)bh * LL + q0) * DKK;
    const float* Kp = K + (size_t)bh * LL * DKK;
    const float* Vp = V + (size_t)bh * LL * DKK;
    const float* Sb = S + ((size_t)bh * LL + q0) * LL;

    auto loadK = [&](int t) {
        #pragma unroll
        for (int i = 0; i < 4; i++) {
            int idx = tid + i * 256;
            int r = idx >> 4, d4 = (idx & 15) << 2;
            cp16(&sm.Ks[r * FQSTR + d4], Kp + (size_t)(t * 64 + r) * DKK + d4);
        }
        cp_commit();
    };
    auto loadV = [&](int t) {
        #pragma unroll
        for (int i = 0; i < 4; i++) {
            int idx = tid + i * 256;
            int r = idx >> 4, d4 = (idx & 15) << 2;
            cp16(&sm.Vs[r * FQSTR + d4], Vp + (size_t)(t * 64 + r) * DKK + d4);
        }
        cp_commit();
    };

    loadK(0);
    loadV(0);

    #pragma unroll
    for (int i = 0; i < 4; i++) {
        int idx = tid + i * 256;
        int r = idx >> 4, d4 = (idx & 15) << 2;
        float4 v = *(const float4*)(Qp + (size_t)r * DKK + d4);
        int kk = d4 >> 3, hh = (d4 >> 2) & 1;
        float* p = sm.Qs + ((kk * 4) * FQSTR + r) * 2 + hh;
        p[0]          = tf32f(v.x * 0.125f);
        p[FQSTR*2]    = tf32f(v.y * 0.125f);
        p[FQSTR*4]    = tf32f(v.z * 0.125f);
        p[FQSTR*6]    = tf32f(v.w * 0.125f);
    }

    float accO[2][2][4];
    #pragma unroll
    for (int i = 0; i < 2; i++)
        #pragma unroll
        for (int j = 0; j < 2; j++)
            #pragma unroll
            for (int q = 0; q < 4; q++) accO[i][j][q] = 0.f;

    float rowM = -1e30f, rowL = 0.f;
    const int myrow = tid >> 2, quarter = tid & 3;

    for (int t = 0; t < 16; t++) {
        float accS[2][2][4];
        const int kb = t * 64;
        #pragma unroll
        for (int i = 0; i < 2; i++) {
            int r = wm * 32 + i * 16 + g;
            #pragma unroll
            for (int j = 0; j < 2; j++) {
                int col = kb + wn * 16 + j * 8 + t4 * 2;
                float2 b0 = *(const float2*)(Sb + (size_t)r * LL + col);
                float2 b1 = *(const float2*)(Sb + (size_t)(r + 8) * LL + col);
                accS[i][j][0] = b0.x; accS[i][j][1] = b0.y;
                accS[i][j][2] = b1.x; accS[i][j][3] = b1.y;
            }
        }

        cp_wait<1>();
        __syncthreads();

        #pragma unroll
        for (int ks = 0; ks < 8; ks++) {
            const int kc = ks * 8 + t4;
            unsigned aF[2][4];
            #pragma unroll
            for (int i = 0; i < 2; i++) {
                int mb = wm * 32 + i * 16 + g;
                float2 lo = *(const float2*)(sm.Qs + ((ks * 4 + t4) * FQSTR + mb) * 2);
                float2 hi = *(const float2*)(sm.Qs + ((ks * 4 + t4) * FQSTR + mb + 8) * 2);
                aF[i][0] = __float_as_uint(lo.x); aF[i][1] = __float_as_uint(hi.x);
                aF[i][2] = __float_as_uint(lo.y); aF[i][3] = __float_as_uint(hi.y);
            }
            unsigned bF[2][2];
            #pragma unroll
            for (int j = 0; j < 2; j++) {
                int nb = wn * 16 + j * 8 + g;
                bF[j][0] = __float_as_uint(sm.Ks[nb * FQSTR + kc]);
                bF[j][1] = __float_as_uint(sm.Ks[nb * FQSTR + kc + 4]);
            }
            #pragma unroll
            for (int i = 0; i < 2; i++)
                #pragma unroll
                for (int j = 0; j < 2; j++)
                    mma_tf32(accS[i][j], aF[i], bF[j]);
        }

        {
            const int cc = (t4 & 1) * 2, hh = t4 >> 1;
            #pragma unroll
            for (int i = 0; i < 2; i++) {
                int r = wm * 32 + i * 16 + g;
                #pragma unroll
                for (int j = 0; j < 2; j++) {
                    int colk = (wn * 16 + j * 8 + t4 * 2) >> 3;
                    int e = (colk * 4 + cc) * FQSTR + r;
                    sm.Ss[e * 2 + hh]                 = accS[i][j][0];
                    sm.Ss[(e + FQSTR) * 2 + hh]       = accS[i][j][1];
                    sm.Ss[(e + 8) * 2 + hh]           = accS[i][j][2];
                    sm.Ss[(e + FQSTR + 8) * 2 + hh]   = accS[i][j][3];
                }
            }
        }
        __syncthreads();
        if (t + 1 < 16) loadK(t + 1);

        {
            float2 vals[8];
            float mx = -1e30f;
            #pragma unroll
            for (int e = 0; e < 8; e++) {
                int kk = 2 * quarter + (e >> 2), cc2 = e & 3;
                vals[e] = *(const float2*)(sm.Ss + ((kk * 4 + cc2) * FQSTR + myrow) * 2);
                mx = fmaxf(mx, fmaxf(vals[e].x, vals[e].y));
            }
            mx = fmaxf(mx, __shfl_xor_sync(0xffffffffu, mx, 1));
            mx = fmaxf(mx, __shfl_xor_sync(0xffffffffu, mx, 2));
            float mNew = fmaxf(rowM, mx);
            float scale = __expf(rowM - mNew);
            float sum = 0.f;
            #pragma unroll
            for (int e = 0; e < 8; e++) {
                vals[e].x = __expf(vals[e].x - mNew);
                vals[e].y = __expf(vals[e].y - mNew);
                sum += vals[e].x + vals[e].y;
                int kk = 2 * quarter + (e >> 2), cc2 = e & 3;
                *(float2*)(sm.Ss + ((kk * 4 + cc2) * FQSTR + myrow) * 2) =
                    make_float2(vals[e].x, vals[e].y);
            }
            sum += __shfl_xor_sync(0xffffffffu, sum, 1);
            sum += __shfl_xor_sync(0xffffffffu, sum, 2);
            rowL = rowL * scale + sum;
            rowM = mNew;
            if (quarter == 0) sm.rowScale[myrow] = scale;
        }
        if (t + 1 < 16) cp_wait<1>(); else cp_wait<0>();
        __syncthreads();

        #pragma unroll
        for (int i = 0; i < 2; i++) {
            int r = wm * 32 + i * 16 + g;
            float s0 = sm.rowScale[r], s1 = sm.rowScale[r + 8];
            #pragma unroll
            for (int j = 0; j < 2; j++) {
                accO[i][j][0] *= s0; accO[i][j][1] *= s0;
                accO[i][j][2] *= s1; accO[i][j][3] *= s1;
            }
        }

        #pragma unroll
        for (int ks = 0; ks < 8; ks++) {
            const int kc = ks * 8 + t4;
            unsigned aF[2][4];
            #pragma unroll
            for (int i = 0; i < 2; i++) {
                int mb = wm * 32 + i * 16 + g;
                float2 lo = *(const float2*)(sm.Ss + ((ks * 4 + t4) * FQSTR + mb) * 2);
                float2 hi = *(const float2*)(sm.Ss + ((ks * 4 + t4) * FQSTR + mb + 8) * 2);
                aF[i][0] = __float_as_uint(lo.x); aF[i][1] = __float_as_uint(hi.x);
                aF[i][2] = __float_as_uint(lo.y); aF[i][3] = __float_as_uint(hi.y);
            }
            unsigned bF[2][2];
            #pragma unroll
            for (int j = 0; j < 2; j++) {
                int nb = wn * 16 + j * 8 + g;
                bF[j][0] = __float_as_uint(sm.Vs[kc * FQSTR + nb]);
                bF[j][1] = __float_as_uint(sm.Vs[(kc + 4) * FQSTR + nb]);
            }
            #pragma unroll
            for (int i = 0; i < 2; i++)
                #pragma unroll
                for (int j = 0; j < 2; j++)
                    mma_tf32(accO[i][j], aF[i], bF[j]);
        }
        __syncthreads();
        if (t + 1 < 16) loadV(t + 1);
    }

    if (quarter == 0) sm.rowInv[myrow] = 1.f / rowL;
    __syncthreads();

    float* Op = O + ((size_t)b * LL + q0) * DM + h * DKK;
    #pragma unroll
    for (int i = 0; i < 2; i++) {
        int r = wm * 32 + i * 16 + g;
        float i0 = sm.rowInv[r], i1 = sm.rowInv[r + 8];
        #pragma unroll
        for (int j = 0; j < 2; j++) {
            int col = wn * 16 + j * 8 + t4 * 2;
            *(float2*)(Op + (size_t)r * DM + col) =
                make_float2(accO[i][j][0] * i0, accO[i][j][1] * i0);
            *(float2*)(Op + (size_t)(r + 8) * DM + col) =
                make_float2(accO[i][j][2] * i1, accO[i][j][3] * i1);
        }
    }
}

// ---------------- layernorm over last dim (768) ----------------
__global__ __launch_bounds__(256) void layernorm_kernel(
    const float* __restrict__ X, const float* __restrict__ g, const float* __restrict__ be,
    float* __restrict__ Y)
{
    __shared__ float red[256];
    const size_t row = blockIdx.x;
    const float* p = X + row * DM;
    float* o = Y + row * DM;
    const int tid = threadIdx.x;
    float v[3];
    float s = 0.f;
    #pragma unroll
    for (int i = 0; i < 3; i++) { v[i] = p[tid + i*256]; s += v[i]; }
    red[tid] = s; __syncthreads();
    for (int st = 128; st > 0; st >>= 1) { if (tid < st) red[tid] += red[tid+st]; __syncthreads(); }
    float mean = red[0] * (1.f/DM); __syncthreads();
    float sq = 0.f;
    #pragma unroll
    for (int i = 0; i < 3; i++) { float d = v[i] - mean; sq += d*d; }
    red[tid] = sq; __syncthreads();
    for (int st = 128; st > 0; st >>= 1) { if (tid < st) red[tid] += red[tid+st]; __syncthreads(); }
    float rstd = rsqrtf(red[0] * (1.f/DM) + 1e-5f);
    #pragma unroll
    for (int i = 0; i < 3; i++) {
        int c = tid + i*256;
        o[c] = (v[i] - mean) * rstd * g[c] + be[c];
    }
}

// ---------------- launch ----------------
extern "C" void kernel_launch(void* const* d_in, const int* in_sizes, int n_in,
                              void* d_out, int out_size)
{
    const float* src = (const float*)d_in[0];
    const float* sx  = (const float*)d_in[1];
    const float* sy  = (const float*)d_in[2];
    const float* Wq  = (const float*)d_in[3];  const float* bq  = (const float*)d_in[4];
    const float* Wk  = (const float*)d_in[5];  const float* bk  = (const float*)d_in[6];
    const float* Wv  = (const float*)d_in[7];  const float* bv  = (const float*)d_in[8];
    const float* Wo  = (const float*)d_in[9];  const float* bo  = (const float*)d_in[10];
    const float* P1  = (const float*)d_in[11]; const float* pb1 = (const float*)d_in[12];
    const float* P2  = (const float*)d_in[13]; const float* pb2 = (const float*)d_in[14];
    const float* W1  = (const float*)d_in[15]; const float* b1  = (const float*)d_in[16];
    const float* W2  = (const float*)d_in[17]; const float* b2  = (const float*)d_in[18];
    const float* g1  = (const float*)d_in[19]; const float* be1 = (const float*)d_in[20];
    const float* g2  = (const float*)d_in[21]; const float* be2 = (const float*)d_in[22];
    float* out = (float*)d_out;

    float *Q, *K, *V, *S, *O, *Xres, *X1, *H1;
    cudaGetSymbolAddress((void**)&Q,    g_Q);
    cudaGetSymbolAddress((void**)&K,    g_K);
    cudaGetSymbolAddress((void**)&V,    g_V);
    cudaGetSymbolAddress((void**)&S,    g_S);
    cudaGetSymbolAddress((void**)&O,    g_O);
    cudaGetSymbolAddress((void**)&Xres, g_Xres);
    cudaGetSymbolAddress((void**)&X1,   g_X1);
    cudaGetSymbolAddress((void**)&H1,   g_H1);

    cudaFuncSetAttribute(flash64_kernel, cudaFuncAttributeMaxDynamicSharedMemorySize,
                         (int)FL64_SMEM_BYTES);
    cudaFuncSetAttribute(pbqkv_kernel, cudaFuncAttributeMaxDynamicSharedMemorySize,
                         TG_SMEM(128, 128));
    cudaFuncSetAttribute(tgemm<1, 128, 128>, cudaFuncAttributeMaxDynamicSharedMemorySize,
                         TG_SMEM(128, 128));
    cudaFuncSetAttribute(tgemm<2, 128, 64>, cudaFuncAttributeMaxDynamicSharedMemorySize,
                         TG_SMEM(128, 64));

    // 1) fused: relative-position bias -> S  ||  QKV projections -> Q,K,V
    pbqkv_kernel<<<PBQKV_GRID, 256, TG_SMEM(128, 128)>>>(
        src, Wq, bq, Wk, bk, Wv, bv, Q, K, V,
        sx, sy, P1, pb1, P2, pb2, S);

    // 2) flash attention: softmax(QK^T/8 + bias) @ V -> O
    flash64_kernel<<<dim3(LL/64, BB*NH), 256, FL64_SMEM_BYTES>>>(S, Q, K, V, O);

    // 3) Xres = src + O @ Wo + bo ; LN1 -> X1
    tgemm<2, 128, 64><<<dim3(DM/64, ROWS/128, 1), 256, TG_SMEM(128, 64)>>>(
        O, DM, Wo, DM, bo, src, Xres, DM, DM,
        nullptr, nullptr, nullptr, nullptr, nullptr, nullptr);
    layernorm_kernel<<<ROWS, 256>>>(Xres, g1, be1, X1);

    // 4) FFN
    tgemm<1, 128, 128><<<dim3(FFD/128, ROWS/128, 1), 256, TG_SMEM(128, 128)>>>(
        X1, DM, W1, FFD, b1, nullptr, H1, FFD, DM,
        nullptr, nullptr, nullptr, nullptr, nullptr, nullptr);
    tgemm<2, 128, 64><<<dim3(DM/64, ROWS/128, 1), 256, TG_SMEM(128, 64)>>>(
        H1, FFD, W2, DM, b2, X1, Xres, DM, FFD,
        nullptr, nullptr, nullptr, nullptr, nullptr, nullptr);

    // 5) LN2 -> output
    layernorm_kernel<<<ROWS, 256>>>(Xres, g2, be2, out);
}

// round 15
// speedup vs baseline: 1.0489x; 1.0489x over previous
#include <cuda_runtime.h>
#include <math.h>

#define BB 2
#define LL 1024
#define DM 768
#define NH 12
#define DKK 64
#define FFD 3072
#define PH 32
#define ROWS (BB*LL)

// ---------------- scratch ----------------
__device__ float g_Q[BB*NH*LL*DKK];
__device__ float g_K[BB*NH*LL*DKK];
__device__ float g_V[BB*NH*LL*DKK];
__device__ float g_S[(size_t)BB*NH*LL*LL];
__device__ float g_O[BB*LL*DM];
__device__ float g_Xres[BB*LL*DM];
__device__ float g_X1[BB*LL*DM];
__device__ float g_H1[BB*LL*FFD];

// ---------------- helpers ----------------
__device__ __forceinline__ unsigned tf32u(float x) {
    unsigned u;
    asm("cvt.rna.tf32.f32 %0, %1;" : "=r"(u) : "f"(x));
    return u;
}
__device__ __forceinline__ float tf32f(float x) { return __uint_as_float(tf32u(x)); }

// mma consumes raw fp32 bits as tf32 (HW truncates low mantissa bits)
__device__ __forceinline__ void mma_tf32(float* c, const unsigned* a, const unsigned* b) {
    asm volatile(
        "mma.sync.aligned.m16n8k8.row.col.f32.tf32.tf32.f32 "
        "{%0,%1,%2,%3}, {%4,%5,%6,%7}, {%8,%9}, {%0,%1,%2,%3};"
        : "+f"(c[0]), "+f"(c[1]), "+f"(c[2]), "+f"(c[3])
        : "r"(a[0]), "r"(a[1]), "r"(a[2]), "r"(a[3]), "r"(b[0]), "r"(b[1]));
}

__device__ __forceinline__ void ldmatrix_x4(unsigned& r0, unsigned& r1,
                                            unsigned& r2, unsigned& r3, unsigned addr) {
    asm volatile("ldmatrix.sync.aligned.m8n8.x4.shared.b16 {%0,%1,%2,%3}, [%4];"
        : "=r"(r0), "=r"(r1), "=r"(r2), "=r"(r3) : "r"(addr));
}

__device__ __forceinline__ unsigned smem_u32(const void* p) {
    return (unsigned)__cvta_generic_to_shared(p);
}

__device__ __forceinline__ void cp16(float* dst_smem, const float* src) {
    unsigned d = (unsigned)__cvta_generic_to_shared(dst_smem);
    asm volatile("cp.async.cg.shared.global [%0], [%1], 16;" :: "r"(d), "l"(src));
}
__device__ __forceinline__ void cp_commit() { asm volatile("cp.async.commit_group;"); }
template<int N> __device__ __forceinline__ void cp_wait() {
    asm volatile("cp.async.wait_group %0;" :: "n"(N));
}

// ---------------- tensor-core GEMM body: BK=32, multi-stage cp.async, ldmatrix A ----
// EPI 1: relu(+bias)  2: +bias +R residual  3: fused QKV scatter
// 8 warps = 2(m) x 4(n). Warp tile (BM/2) x (BN/4).
// (64,64) config uses a 4-stage pipeline; others 3-stage.
template<int EPI, int BM, int BN>
__device__ __forceinline__ void tgemm_body(
    int bxi, int byi,
    const float* __restrict__ A, int lda,
    const float* __restrict__ B, int ldb,
    const float* __restrict__ bias,
    const float* __restrict__ Rres,
    float* __restrict__ C, int ldc,
    int K,
    const float* __restrict__ B1, const float* __restrict__ B2,
    const float* __restrict__ bias1, const float* __restrict__ bias2,
    float* __restrict__ C1, float* __restrict__ C2,
    float* dynsm)
{
    constexpr int MI  = BM / 32;
    constexpr int NT  = BN / 32;
    constexpr int WNS = BN / 4;
    constexpr int ST  = (BM == 64 && BN == 64) ? 4 : 3;
    constexpr int AP  = 36;
    constexpr int BP  = BN + 8;
    constexpr int ASZ = BM * AP;
    constexpr int BSZ = 32 * BP;
    float* As = dynsm;
    float* Bs = dynsm + ST * ASZ;

    const int tid = threadIdx.x;
    const int lane = tid & 31, w = tid >> 5;
    const int wm = w & 1, wn = w >> 1;
    const int g = lane >> 2, t4 = lane & 3;
    int bx = bxi;
    const int m0 = byi * BM;

    const float* Ap = A;
    const float* Bp = B; const float* biasp = bias; float* Cp = C;
    if (EPI == 3) {
        int sel = bx / 6; bx -= sel * 6;
        Bp    = sel == 0 ? B    : (sel == 1 ? B1    : B2);
        biasp = sel == 0 ? bias : (sel == 1 ? bias1 : bias2);
        Cp    = sel == 0 ? C    : (sel == 1 ? C1    : C2);
    }
    const int n0 = bx * BN;

    float acc[MI][NT][4];
    #pragma unroll
    for (int i = 0; i < MI; i++)
        #pragma unroll
        for (int j = 0; j < NT; j++)
            #pragma unroll
            for (int q = 0; q < 4; q++) acc[i][j][q] = 0.f;

    auto loadA = [&](int kt, int st) {
        #pragma unroll
        for (int i = 0; i < BM / 32; i++) {
            int idx = tid + i * 256;
            int m = idx >> 3, k4 = (idx & 7) << 2;
            cp16(&As[st * ASZ + m * AP + k4], Ap + (size_t)(m0 + m) * lda + kt + k4);
        }
    };
    auto loadB = [&](int kt, int st) {
        if (BN == 128) {
            #pragma unroll
            for (int i = 0; i < 4; i++) {
                int idx = tid + i * 256;
                int k = idx >> 5, n4 = (idx & 31) << 2;
                cp16(&Bs[st * BSZ + k * BP + n4], Bp + (size_t)(kt + k) * ldb + n0 + n4);
            }
        } else {
            #pragma unroll
            for (int i = 0; i < 2; i++) {
                int idx = tid + i * 256;
                int k = idx >> 4, n4 = (idx & 15) << 2;
                cp16(&Bs[st * BSZ + k * BP + n4], Bp + (size_t)(kt + k) * ldb + n0 + n4);
            }
        }
    };
    const int lmRow = lane & 15;
    const int lmCol = (lane >> 4) << 2;
    auto ldA = [&](int st, int kk, unsigned (&aF)[MI][4]) {
        #pragma unroll
        for (int i = 0; i < MI; i++) {
            int mb0 = wm * (MI * 16) + i * 16;
            unsigned addr = smem_u32(
                &As[st * ASZ + (mb0 + lmRow) * AP + kk * 8 + lmCol]);
            ldmatrix_x4(aF[i][0], aF[i][1], aF[i][2], aF[i][3], addr);
        }
    };
    auto ldB = [&](int st, int kk, unsigned (&bF)[NT][2]) {
        const int kc = kk * 8 + t4;
        #pragma unroll
        for (int j = 0; j < NT; j++) {
            int nb = wn * WNS + j * 8 + g;
            bF[j][0] = __float_as_uint(Bs[st * BSZ + kc * BP + nb]);
            bF[j][1] = __float_as_uint(Bs[st * BSZ + (kc + 4) * BP + nb]);
        }
    };
    auto compute = [&](int st) {
        unsigned aF[MI][4];
        unsigned bF[2][NT][2];
        ldB(st, 0, bF[0]);
        #pragma unroll
        for (int kk = 0; kk < 4; kk++) {
            const int cb = kk & 1;
            ldA(st, kk, aF);
            if (kk < 3) ldB(st, kk + 1, bF[cb ^ 1]);
            #pragma unroll
            for (int i = 0; i < MI; i++)
                #pragma unroll
                for (int j = 0; j < NT; j++)
                    mma_tf32(acc[i][j], aF[i], bF[cb][j]);
        }
    };

    const int nt = K >> 5;
    loadA(0, 0); loadB(0, 0); cp_commit();
    if (nt > 1) { loadA(32, 1); loadB(32, 1); cp_commit(); }
    if (ST == 4 && nt > 2) { loadA(64, 2); loadB(64, 2); cp_commit(); }
    for (int t = 0; t < nt; t++) {
        if (t + ST - 1 < nt)                 cp_wait<ST - 2>();
        else if (ST == 4 && t + 2 < nt)      cp_wait<1>();
        else                                 cp_wait<0>();
        __syncthreads();
        compute(t % ST);
        if (t + ST - 1 < nt) {
            int st = (t + ST - 1) % ST;
            loadA((t + ST - 1) << 5, st);
            loadB((t + ST - 1) << 5, st);
            cp_commit();
        }
    }

    auto epi = [&](int row, int col, float2 v) {
        float2 bb = *(const float2*)(biasp + col);
        v.x += bb.x; v.y += bb.y;
        if (EPI == 1) { v.x = fmaxf(v.x, 0.f); v.y = fmaxf(v.y, 0.f); }
        if (EPI == 2) {
            float2 r = *(const float2*)(Rres + (size_t)row * ldc + col);
            v.x += r.x; v.y += r.y;
        }
        if (EPI == 3) {
            int h = col >> 6, d = col & 63;
            float* dst = Cp + ((((size_t)(row >> 10) * NH + h) * LL + (row & 1023)) * DKK + d);
            *(float2*)dst = v;
            return;
        }
        *(float2*)(Cp + (size_t)row * ldc + col) = v;
    };

    #pragma unroll
    for (int i = 0; i < MI; i++) {
        int r0 = m0 + wm * (MI * 16) + i * 16 + g;
        #pragma unroll
        for (int j = 0; j < NT; j++) {
            int col = n0 + wn * WNS + j * 8 + t4 * 2;
            epi(r0,     col, make_float2(acc[i][j][0], acc[i][j][1]));
            epi(r0 + 8, col, make_float2(acc[i][j][2], acc[i][j][3]));
        }
    }
}

#define TG_SMEM(BM, BN) ((((BM) == 64 && (BN) == 64) ? 4 : 3) * ((BM) * 36 + 32 * ((BN) + 8)) * 4)

template<int EPI, int BM, int BN>
__global__ __launch_bounds__(256, (BM == 64 && BN == 64) ? 3 : 2) void tgemm(
    const float* __restrict__ A, int lda,
    const float* __restrict__ B, int ldb,
    const float* __restrict__ bias,
    const float* __restrict__ Rres,
    float* __restrict__ C, int ldc,
    int K,
    const float* __restrict__ B1, const float* __restrict__ B2,
    const float* __restrict__ bias1, const float* __restrict__ bias2,
    float* __restrict__ C1, float* __restrict__ C2)
{
    extern __shared__ float dynsm[];
    tgemm_body<EPI, BM, BN>(blockIdx.x, blockIdx.y, A, lda, B, ldb, bias, Rres,
                            C, ldc, K, B1, B2, bias1, bias2, C1, C2, dynsm);
}

// ---------------- posbias body: layer-1 scalar, layer-2 via tf32 mma ----------------
__device__ __forceinline__ void posbias_body(
    int kx, int qy, int b,
    const float* __restrict__ sx, const float* __restrict__ sy,
    const float* __restrict__ P1, const float* __restrict__ pb1,
    const float* __restrict__ P2, const float* __restrict__ pb2,
    float* __restrict__ S, float* dynsm)
{
    constexpr int HSTR = 260;
    constexpr int PSTR = 20;
    float* Hs   = dynsm;
    float* Ps   = Hs + 16 * HSTR * 2;
    float* sP1  = Ps + 16 * PSTR * 2;
    float* sPb1 = sP1 + 64;
    float* sPb2 = sPb1 + 32;
    float* qx   = sPb2 + 16;
    float* qy_  = qx + 16;
    float* kxp  = qy_ + 16;
    float* kyp  = kxp + 16;

    const int q0 = qy * 16, k0 = kx * 16;
    const int tid = threadIdx.x;
    const int lane = tid & 31, w = tid >> 5;
    const int g = lane >> 2, t4 = lane & 3;

    if (tid < 64) sP1[tid] = P1[tid];
    if (tid < 32) sPb1[tid] = pb1[tid];
    if (tid < 16) {
        sPb2[tid] = tid < NH ? pb2[tid] : 0.f;
        qx[tid]  = sx[b*LL + q0 + tid];
        qy_[tid] = sy[b*LL + q0 + tid];
        kxp[tid] = sx[b*LL + k0 + tid];
        kyp[tid] = sy[b*LL + k0 + tid];
    }
    #pragma unroll
    for (int ii = 0; ii < 2; ii++) {
        int v = tid + ii * 256;
        int n = v & 15, k = v >> 4;
        float val = (n < NH) ? P2[k * NH + n] : 0.f;
        int kk = k >> 3, hh = (k >> 2) & 1, cc = k & 3;
        Ps[((kk * 4 + cc) * PSTR + n) * 2 + hh] = val;
    }
    __syncthreads();

    {
        int qq = tid >> 4, kq = tid & 15;
        float rx = fminf(fmaxf(qx[qq] - kxp[kq], -1000.f), 1000.f) * 0.001f;
        float ry = fminf(fmaxf(qy_[qq] - kyp[kq], -1000.f), 1000.f) * 0.001f;
        #pragma unroll
        for (int kk = 0; kk < 4; kk++)
            #pragma unroll
            for (int cc = 0; cc < 4; cc++) {
                int j0 = kk * 8 + cc, j1 = j0 + 4;
                float h0 = fmaxf(fmaf(rx, sP1[j0], fmaf(ry, sP1[32+j0], sPb1[j0])), 0.f);
                float h1 = fmaxf(fmaf(rx, sP1[j1], fmaf(ry, sP1[32+j1], sPb1[j1])), 0.f);
                *(float2*)(&Hs[((kk * 4 + cc) * HSTR + tid) * 2]) = make_float2(h0, h1);
            }
    }
    __syncthreads();

    float acc[2][2][4];
    #pragma unroll
    for (int i = 0; i < 2; i++)
        #pragma unroll
        for (int j = 0; j < 2; j++)
            #pragma unroll
            for (int q = 0; q < 4; q++) acc[i][j][q] = 0.f;

    #pragma unroll
    for (int ks = 0; ks < 4; ks++) {
        unsigned aF[2][4];
        #pragma unroll
        for (int i = 0; i < 2; i++) {
            int mb = (w * 2 + i) * 16 + g;
            float2 lo = *(const float2*)(&Hs[((ks * 4 + t4) * HSTR + mb) * 2]);
            float2 hi = *(const float2*)(&Hs[((ks * 4 + t4) * HSTR + mb + 8) * 2]);
            aF[i][0] = __float_as_uint(lo.x); aF[i][1] = __float_as_uint(hi.x);
            aF[i][2] = __float_as_uint(lo.y); aF[i][3] = __float_as_uint(hi.y);
        }
        unsigned bF[2][2];
        #pragma unroll
        for (int j = 0; j < 2; j++) {
            float2 bb = *(const float2*)(&Ps[((ks * 4 + t4) * PSTR + j * 8 + g) * 2]);
            bF[j][0] = __float_as_uint(bb.x); bF[j][1] = __float_as_uint(bb.y);
        }
        #pragma unroll
        for (int i = 0; i < 2; i++)
            #pragma unroll
            for (int j = 0; j < 2; j++)
                mma_tf32(acc[i][j], aF[i], bF[j]);
    }

    #pragma unroll
    for (int i = 0; i < 2; i++) {
        int p0 = (w * 2 + i) * 16 + g;
        int p1 = p0 + 8;
        int q_0 = q0 + (p0 >> 4), k_0 = k0 + (p0 & 15);
        int q_1 = q0 + (p1 >> 4), k_1 = k0 + (p1 & 15);
        #pragma unroll
        for (int j = 0; j < 2; j++) {
            int c0 = j * 8 + t4 * 2, c1 = c0 + 1;
            if (c0 < NH) {
                S[((size_t)(b*NH + c0) * LL + q_0) * LL + k_0] = acc[i][j][0] + sPb2[c0];
                S[((size_t)(b*NH + c0) * LL + q_1) * LL + k_1] = acc[i][j][2] + sPb2[c0];
            }
            if (c1 < NH) {
                S[((size_t)(b*NH + c1) * LL + q_0) * LL + k_0] = acc[i][j][1] + sPb2[c1];
                S[((size_t)(b*NH + c1) * LL + q_1) * LL + k_1] = acc[i][j][3] + sPb2[c1];
            }
        }
    }
}

// ---------------- fused posbias + QKV (heterogeneous grid) ----------------
#define QKV_BLOCKS 288
#define PBQKV_GRID (QKV_BLOCKS + 64*64*BB)

__global__ __launch_bounds__(256, 2) void pbqkv_kernel(
    const float* __restrict__ src,
    const float* __restrict__ Wq, const float* __restrict__ bq,
    const float* __restrict__ Wk, const float* __restrict__ bk,
    const float* __restrict__ Wv, const float* __restrict__ bv,
    float* __restrict__ Q, float* __restrict__ Kq, float* __restrict__ V,
    const float* __restrict__ sx, const float* __restrict__ sy,
    const float* __restrict__ P1, const float* __restrict__ pb1,
    const float* __restrict__ P2, const float* __restrict__ pb2,
    float* __restrict__ S)
{
    extern __shared__ float dynsm[];
    const int bid = blockIdx.x;
    if (bid < QKV_BLOCKS) {
        tgemm_body<3, 128, 128>(bid % 18, bid / 18,
            src, DM, Wq, DM, bq, nullptr, Q, 0, DM,
            Wk, Wv, bk, bv, Kq, V, dynsm);
    } else {
        int p = bid - QKV_BLOCKS;
        posbias_body(p & 63, (p >> 6) & 63, p >> 12,
                     sx, sy, P1, pb1, P2, pb2, S, dynsm);
    }
}

// ---------------- flash64: QK^T + bias + online softmax + PV -----------------
#define FQSTR 68
struct Flash64Smem {
    float Qs[32*FQSTR*2];
    float Ss[32*FQSTR*2];
    float Ks[64*FQSTR];
    float Vs[64*FQSTR];
    float rowScale[64];
    float rowInv[64];
};
#define FL64_SMEM_BYTES sizeof(Flash64Smem)

__global__ __launch_bounds__(256, 3) void flash64_kernel(
    const float* __restrict__ S, const float* __restrict__ Q,
    const float* __restrict__ K, const float* __restrict__ V,
    float* __restrict__ O)
{
    extern __shared__ char smraw[];
    Flash64Smem& sm = *reinterpret_cast<Flash64Smem*>(smraw);

    const int tid = threadIdx.x;
    const int lane = tid & 31, w = tid >> 5;
    const int wm = w & 1, wn = w >> 1;
    const int g = lane >> 2, t4 = lane & 3;
    const int bh = blockIdx.y, b = bh / NH, h = bh % NH;
    const int q0 = blockIdx.x * 64;

    const float* Qp = Q + ((size_t)bh * LL + q0) * DKK;
    const float* Kp = K + (size_t)bh * LL * DKK;
    const float* Vp = V + (size_t)bh * LL * DKK;
    const float* Sb = S + ((size_t)bh * LL + q0) * LL;

    auto loadK = [&](int t) {
        #pragma unroll
        for (int i = 0; i < 4; i++) {
            int idx = tid + i * 256;
            int r = idx >> 4, d4 = (idx & 15) << 2;
            cp16(&sm.Ks[r * FQSTR + d4], Kp + (size_t)(t * 64 + r) * DKK + d4);
        }
        cp_commit();
    };
    auto loadV = [&](int t) {
        #pragma unroll
        for (int i = 0; i < 4; i++) {
            int idx = tid + i * 256;
            int r = idx >> 4, d4 = (idx & 15) << 2;
            cp16(&sm.Vs[r * FQSTR + d4], Vp + (size_t)(t * 64 + r) * DKK + d4);
        }
        cp_commit();
    };

    loadK(0);
    loadV(0);

    #pragma unroll
    for (int i = 0; i < 4; i++) {
        int idx = tid + i * 256;
        int r = idx >> 4, d4 = (idx & 15) << 2;
        float4 v = *(const float4*)(Qp + (size_t)r * DKK + d4);
        int kk = d4 >> 3, hh = (d4 >> 2) & 1;
        float* p = sm.Qs + ((kk * 4) * FQSTR + r) * 2 + hh;
        p[0]          = tf32f(v.x * 0.125f);
        p[FQSTR*2]    = tf32f(v.y * 0.125f);
        p[FQSTR*4]    = tf32f(v.z * 0.125f);
        p[FQSTR*6]    = tf32f(v.w * 0.125f);
    }

    float accO[2][2][4];
    #pragma unroll
    for (int i = 0; i < 2; i++)
        #pragma unroll
        for (int j = 0; j < 2; j++)
            #pragma unroll
            for (int q = 0; q < 4; q++) accO[i][j][q] = 0.f;

    float rowM = -1e30f, rowL = 0.f;
    const int myrow = tid >> 2, quarter = tid & 3;

    for (int t = 0; t < 16; t++) {
        float accS[2][2][4];
        const int kb = t * 64;
        #pragma unroll
        for (int i = 0; i < 2; i++) {
            int r = wm * 32 + i * 16 + g;
            #pragma unroll
            for (int j = 0; j < 2; j++) {
                int col = kb + wn * 16 + j * 8 + t4 * 2;
                float2 b0 = *(const float2*)(Sb + (size_t)r * LL + col);
                float2 b1 = *(const float2*)(Sb + (size_t)(r + 8) * LL + col);
                accS[i][j][0] = b0.x; accS[i][j][1] = b0.y;
                accS[i][j][2] = b1.x; accS[i][j][3] = b1.y;
            }
        }

        cp_wait<1>();
        __syncthreads();

        #pragma unroll
        for (int ks = 0; ks < 8; ks++) {
            const int kc = ks * 8 + t4;
            unsigned aF[2][4];
            #pragma unroll
            for (int i = 0; i < 2; i++) {
                int mb = wm * 32 + i * 16 + g;
                float2 lo = *(const float2*)(sm.Qs + ((ks * 4 + t4) * FQSTR + mb) * 2);
                float2 hi = *(const float2*)(sm.Qs + ((ks * 4 + t4) * FQSTR + mb + 8) * 2);
                aF[i][0] = __float_as_uint(lo.x); aF[i][1] = __float_as_uint(hi.x);
                aF[i][2] = __float_as_uint(lo.y); aF[i][3] = __float_as_uint(hi.y);
            }
            unsigned bF[2][2];
            #pragma unroll
            for (int j = 0; j < 2; j++) {
                int nb = wn * 16 + j * 8 + g;
                bF[j][0] = __float_as_uint(sm.Ks[nb * FQSTR + kc]);
                bF[j][1] = __float_as_uint(sm.Ks[nb * FQSTR + kc + 4]);
            }
            #pragma unroll
            for (int i = 0; i < 2; i++)
                #pragma unroll
                for (int j = 0; j < 2; j++)
                    mma_tf32(accS[i][j], aF[i], bF[j]);
        }

        {
            const int cc = (t4 & 1) * 2, hh = t4 >> 1;
            #pragma unroll
            for (int i = 0; i < 2; i++) {
                int r = wm * 32 + i * 16 + g;
                #pragma unroll
                for (int j = 0; j < 2; j++) {
                    int colk = (wn * 16 + j * 8 + t4 * 2) >> 3;
                    int e = (colk * 4 + cc) * FQSTR + r;
                    sm.Ss[e * 2 + hh]                 = accS[i][j][0];
                    sm.Ss[(e + FQSTR) * 2 + hh]       = accS[i][j][1];
                    sm.Ss[(e + 8) * 2 + hh]           = accS[i][j][2];
                    sm.Ss[(e + FQSTR + 8) * 2 + hh]   = accS[i][j][3];
                }
            }
        }
        __syncthreads();
        if (t + 1 < 16) loadK(t + 1);

        {
            float2 vals[8];
            float mx = -1e30f;
            #pragma unroll
            for (int e = 0; e < 8; e++) {
                int kk = 2 * quarter + (e >> 2), cc2 = e & 3;
                vals[e] = *(const float2*)(sm.Ss + ((kk * 4 + cc2) * FQSTR + myrow) * 2);
                mx = fmaxf(mx, fmaxf(vals[e].x, vals[e].y));
            }
            mx = fmaxf(mx, __shfl_xor_sync(0xffffffffu, mx, 1));
            mx = fmaxf(mx, __shfl_xor_sync(0xffffffffu, mx, 2));
            float mNew = fmaxf(rowM, mx);
            float scale = __expf(rowM - mNew);
            float sum = 0.f;
            #pragma unroll
            for (int e = 0; e < 8; e++) {
                vals[e].x = __expf(vals[e].x - mNew);
                vals[e].y = __expf(vals[e].y - mNew);
                sum += vals[e].x + vals[e].y;
                int kk = 2 * quarter + (e >> 2), cc2 = e & 3;
                *(float2*)(sm.Ss + ((kk * 4 + cc2) * FQSTR + myrow) * 2) =
                    make_float2(vals[e].x, vals[e].y);
            }
            sum += __shfl_xor_sync(0xffffffffu, sum, 1);
            sum += __shfl_xor_sync(0xffffffffu, sum, 2);
            rowL = rowL * scale + sum;
            rowM = mNew;
            if (quarter == 0) sm.rowScale[myrow] = scale;
        }
        if (t + 1 < 16) cp_wait<1>(); else cp_wait<0>();
        __syncthreads();

        #pragma unroll
        for (int i = 0; i < 2; i++) {
            int r = wm * 32 + i * 16 + g;
            float s0 = sm.rowScale[r], s1 = sm.rowScale[r + 8];
            #pragma unroll
            for (int j = 0; j < 2; j++) {
                accO[i][j][0] *= s0; accO[i][j][1] *= s0;
                accO[i][j][2] *= s1; accO[i][j][3] *= s1;
            }
        }

        #pragma unroll
        for (int ks = 0; ks < 8; ks++) {
            const int kc = ks * 8 + t4;
            unsigned aF[2][4];
            #pragma unroll
            for (int i = 0; i < 2; i++) {
                int mb = wm * 32 + i * 16 + g;
                float2 lo = *(const float2*)(sm.Ss + ((ks * 4 + t4) * FQSTR + mb) * 2);
                float2 hi = *(const float2*)(sm.Ss + ((ks * 4 + t4) * FQSTR + mb + 8) * 2);
                aF[i][0] = __float_as_uint(lo.x); aF[i][1] = __float_as_uint(hi.x);
                aF[i][2] = __float_as_uint(lo.y); aF[i][3] = __float_as_uint(hi.y);
            }
            unsigned bF[2][2];
            #pragma unroll
            for (int j = 0; j < 2; j++) {
                int nb = wn * 16 + j * 8 + g;
                bF[j][0] = __float_as_uint(sm.Vs[kc * FQSTR + nb]);
                bF[j][1] = __float_as_uint(sm.Vs[(kc + 4) * FQSTR + nb]);
            }
            #pragma unroll
            for (int i = 0; i < 2; i++)
                #pragma unroll
                for (int j = 0; j < 2; j++)
                    mma_tf32(accO[i][j], aF[i], bF[j]);
        }
        __syncthreads();
        if (t + 1 < 16) loadV(t + 1);
    }

    if (quarter == 0) sm.rowInv[myrow] = 1.f / rowL;
    __syncthreads();

    float* Op = O + ((size_t)b * LL + q0) * DM + h * DKK;
    #pragma unroll
    for (int i = 0; i < 2; i++) {
        int r = wm * 32 + i * 16 + g;
        float i0 = sm.rowInv[r], i1 = sm.rowInv[r + 8];
        #pragma unroll
        for (int j = 0; j < 2; j++) {
            int col = wn * 16 + j * 8 + t4 * 2;
            *(float2*)(Op + (size_t)r * DM + col) =
                make_float2(accO[i][j][0] * i0, accO[i][j][1] * i0);
            *(float2*)(Op + (size_t)(r + 8) * DM + col) =
                make_float2(accO[i][j][2] * i1, accO[i][j][3] * i1);
        }
    }
}

// ---------------- layernorm over last dim (768), warp-shuffle reductions ------------
__global__ __launch_bounds__(256) void layernorm_kernel(
    const float* __restrict__ X, const float* __restrict__ g, const float* __restrict__ be,
    float* __restrict__ Y)
{
    __shared__ float redS[8], redQ[8];
    const size_t row = blockIdx.x;
    const float* p = X + row * DM;
    float* o = Y + row * DM;
    const int tid = threadIdx.x;
    const int lane = tid & 31, w = tid >> 5;
    float v[3];
    float s = 0.f, q = 0.f;
    #pragma unroll
    for (int i = 0; i < 3; i++) {
        v[i] = p[tid + i*256];
        s += v[i];
        q = fmaf(v[i], v[i], q);
    }
    #pragma unroll
    for (int d = 16; d > 0; d >>= 1) {
        s += __shfl_xor_sync(0xffffffffu, s, d);
        q += __shfl_xor_sync(0xffffffffu, q, d);
    }
    if (lane == 0) { redS[w] = s; redQ[w] = q; }
    __syncthreads();
    {
        float s8 = redS[lane & 7], q8 = redQ[lane & 7];
        #pragma unroll
        for (int d = 4; d > 0; d >>= 1) {
            s8 += __shfl_xor_sync(0xffffffffu, s8, d);
            q8 += __shfl_xor_sync(0xffffffffu, q8, d);
        }
        s = s8; q = q8;
    }
    float mean = s * (1.f/DM);
    float var  = q * (1.f/DM) - mean * mean;
    float rstd = rsqrtf(var + 1e-5f);
    #pragma unroll
    for (int i = 0; i < 3; i++) {
        int c = tid + i*256;
        o[c] = (v[i] - mean) * rstd * g[c] + be[c];
    }
}

// ---------------- launch ----------------
extern "C" void kernel_launch(void* const* d_in, const int* in_sizes, int n_in,
                              void* d_out, int out_size)
{
    const float* src = (const float*)d_in[0];
    const float* sx  = (const float*)d_in[1];
    const float* sy  = (const float*)d_in[2];
    const float* Wq  = (const float*)d_in[3];  const float* bq  = (const float*)d_in[4];
    const float* Wk  = (const float*)d_in[5];  const float* bk  = (const float*)d_in[6];
    const float* Wv  = (const float*)d_in[7];  const float* bv  = (const float*)d_in[8];
    const float* Wo  = (const float*)d_in[9];  const float* bo  = (const float*)d_in[10];
    const float* P1  = (const float*)d_in[11]; const float* pb1 = (const float*)d_in[12];
    const float* P2  = (const float*)d_in[13]; const float* pb2 = (const float*)d_in[14];
    const float* W1  = (const float*)d_in[15]; const float* b1  = (const float*)d_in[16];
    const float* W2  = (const float*)d_in[17]; const float* b2  = (const float*)d_in[18];
    const float* g1  = (const float*)d_in[19]; const float* be1 = (const float*)d_in[20];
    const float* g2  = (const float*)d_in[21]; const float* be2 = (const float*)d_in[22];
    float* out = (float*)d_out;

    float *Q, *K, *V, *S, *O, *Xres, *X1, *H1;
    cudaGetSymbolAddress((void**)&Q,    g_Q);
    cudaGetSymbolAddress((void**)&K,    g_K);
    cudaGetSymbolAddress((void**)&V,    g_V);
    cudaGetSymbolAddress((void**)&S,    g_S);
    cudaGetSymbolAddress((void**)&O,    g_O);
    cudaGetSymbolAddress((void**)&Xres, g_Xres);
    cudaGetSymbolAddress((void**)&X1,   g_X1);
    cudaGetSymbolAddress((void**)&H1,   g_H1);

    cudaFuncSetAttribute(flash64_kernel, cudaFuncAttributeMaxDynamicSharedMemorySize,
                         (int)FL64_SMEM_BYTES);
    cudaFuncSetAttribute(pbqkv_kernel, cudaFuncAttributeMaxDynamicSharedMemorySize,
                         TG_SMEM(128, 128));
    cudaFuncSetAttribute(tgemm<1, 128, 128>, cudaFuncAttributeMaxDynamicSharedMemorySize,
                         TG_SMEM(128, 128));
    cudaFuncSetAttribute(tgemm<2, 64, 64>, cudaFuncAttributeMaxDynamicSharedMemorySize,
                         TG_SMEM(64, 64));

    // 1) fused: relative-position bias -> S  ||  QKV projections -> Q,K,V
    pbqkv_kernel<<<PBQKV_GRID, 256, TG_SMEM(128, 128)>>>(
        src, Wq, bq, Wk, bk, Wv, bv, Q, K, V,
        sx, sy, P1, pb1, P2, pb2, S);

    // 2) flash attention: softmax(QK^T/8 + bias) @ V -> O
    flash64_kernel<<<dim3(LL/64, BB*NH), 256, FL64_SMEM_BYTES>>>(S, Q, K, V, O);

    // 3) Xres = src + O @ Wo + bo ; LN1 -> X1
    tgemm<2, 64, 64><<<dim3(DM/64, ROWS/64, 1), 256, TG_SMEM(64, 64)>>>(
        O, DM, Wo, DM, bo, src, Xres, DM, DM,
        nullptr, nullptr, nullptr, nullptr, nullptr, nullptr);
    layernorm_kernel<<<ROWS, 256>>>(Xres, g1, be1, X1);

    // 4) FFN
    tgemm<1, 128, 128><<<dim3(FFD/128, ROWS/128, 1), 256, TG_SMEM(128, 128)>>>(
        X1, DM, W1, FFD, b1, nullptr, H1, FFD, DM,
        nullptr, nullptr, nullptr, nullptr, nullptr, nullptr);
    tgemm<2, 64, 64><<<dim3(DM/64, ROWS/64, 1), 256, TG_SMEM(64, 64)>>>(
        H1, FFD, W2, DM, b2, X1, Xres, DM, FFD,
        nullptr, nullptr, nullptr, nullptr, nullptr, nullptr);

    // 5) LN2 -> output
    layernorm_kernel<<<ROWS, 256>>>(Xres, g2, be2, out);
}

// round 16
// speedup vs baseline: 1.3027x; 1.2420x over previous
#include <cuda_runtime.h>
#include <cuda_fp16.h>
#include <math.h>

#define BB 2
#define LL 1024
#define DM 768
#define NH 12
#define DKK 64
#define FFD 3072
#define PH 32
#define ROWS (BB*LL)

// ---------------- scratch ----------------
__device__ float g_Q[BB*NH*LL*DKK];
__device__ float g_K[BB*NH*LL*DKK];
__device__ float g_V[BB*NH*LL*DKK];
__device__ float g_S[(size_t)BB*NH*LL*LL];
__device__ float g_Xres[BB*LL*DM];
__device__ float g_X1[BB*LL*DM];
__device__ __half g_srcH[ROWS*DM];
__device__ __half g_WqH[DM*DM];
__device__ __half g_WkH[DM*DM];
__device__ __half g_WvH[DM*DM];
__device__ __half g_WoH[DM*DM];
__device__ __half g_W1H[DM*FFD];
__device__ __half g_W2H[FFD*DM];
__device__ __half g_OH[ROWS*DM];
__device__ __half g_X1H[ROWS*DM];
__device__ __half g_H1H[(size_t)ROWS*FFD];

// ---------------- helpers ----------------
__device__ __forceinline__ unsigned tf32u(float x) {
    unsigned u;
    asm("cvt.rna.tf32.f32 %0, %1;" : "=r"(u) : "f"(x));
    return u;
}
__device__ __forceinline__ float tf32f(float x) { return __uint_as_float(tf32u(x)); }

__device__ __forceinline__ void mma_tf32(float* c, const unsigned* a, const unsigned* b) {
    asm volatile(
        "mma.sync.aligned.m16n8k8.row.col.f32.tf32.tf32.f32 "
        "{%0,%1,%2,%3}, {%4,%5,%6,%7}, {%8,%9}, {%0,%1,%2,%3};"
        : "+f"(c[0]), "+f"(c[1]), "+f"(c[2]), "+f"(c[3])
        : "r"(a[0]), "r"(a[1]), "r"(a[2]), "r"(a[3]), "r"(b[0]), "r"(b[1]));
}

__device__ __forceinline__ void mma_f16(float* c, const unsigned* a, const unsigned* b) {
    asm volatile(
        "mma.sync.aligned.m16n8k16.row.col.f32.f16.f16.f32 "
        "{%0,%1,%2,%3}, {%4,%5,%6,%7}, {%8,%9}, {%0,%1,%2,%3};"
        : "+f"(c[0]), "+f"(c[1]), "+f"(c[2]), "+f"(c[3])
        : "r"(a[0]), "r"(a[1]), "r"(a[2]), "r"(a[3]), "r"(b[0]), "r"(b[1]));
}

__device__ __forceinline__ void ldmatrix_x4(unsigned& r0, unsigned& r1,
                                            unsigned& r2, unsigned& r3, unsigned addr) {
    asm volatile("ldmatrix.sync.aligned.m8n8.x4.shared.b16 {%0,%1,%2,%3}, [%4];"
        : "=r"(r0), "=r"(r1), "=r"(r2), "=r"(r3) : "r"(addr));
}

__device__ __forceinline__ unsigned smem_u32(const void* p) {
    return (unsigned)__cvta_generic_to_shared(p);
}

__device__ __forceinline__ void cp16(void* dst_smem, const void* src) {
    unsigned d = (unsigned)__cvta_generic_to_shared(dst_smem);
    asm volatile("cp.async.cg.shared.global [%0], [%1], 16;" :: "r"(d), "l"(src));
}
__device__ __forceinline__ void cp_commit() { asm volatile("cp.async.commit_group;"); }
template<int N> __device__ __forceinline__ void cp_wait() {
    asm volatile("cp.async.wait_group %0;" :: "n"(N));
}

// ---------------- prep: fp32 -> fp16 conversions ----------------
// src row-major; weights k-pair-interleaved: Wh[(k>>1)*2N + n*2 + (k&1)]
#define PREP_GRID 4224
__global__ __launch_bounds__(256) void prep_kernel(
    const float* __restrict__ src,
    const float* __restrict__ Wq, const float* __restrict__ Wk,
    const float* __restrict__ Wv, const float* __restrict__ Wo,
    const float* __restrict__ W1, const float* __restrict__ W2,
    __half* __restrict__ srcH,
    __half* __restrict__ WqH, __half* __restrict__ WkH,
    __half* __restrict__ WvH, __half* __restrict__ WoH,
    __half* __restrict__ W1H, __half* __restrict__ W2H)
{
    int bid = blockIdx.x;
    if (bid < 768) {
        int base = bid * 2048;
        for (int i = threadIdx.x; i < 2048; i += 256)
            srcH[base + i] = __float2half(src[base + i]);
        return;
    }
    bid -= 768;
    const float* W; __half* Wh; int N;
    if      (bid < 288)  { W = Wq; Wh = WqH; N = 768; }
    else if (bid < 576)  { W = Wk; Wh = WkH; N = 768;  bid -= 288; }
    else if (bid < 864)  { W = Wv; Wh = WvH; N = 768;  bid -= 576; }
    else if (bid < 1152) { W = Wo; Wh = WoH; N = 768;  bid -= 864; }
    else if (bid < 2304) { W = W1; Wh = W1H; N = 3072; bid -= 1152; }
    else                 { W = W2; Wh = WvH == nullptr ? nullptr : W2H; N = 768; bid -= 2304; }
    int base = bid * 2048;
    for (int i = threadIdx.x; i < 2048; i += 256) {
        int e = base + i;
        int k = e / N, n = e - k * N;
        Wh[(size_t)(k >> 1) * (2 * N) + n * 2 + (k & 1)] = __float2half(W[e]);
    }
}

// ---------------- fp16 tensor-core GEMM body: BK=32, m16n8k16 ----------------
// EPI 1: relu(+bias), fp16 out   2: +bias +R residual, fp32 out
//     3: fused QKV scatter, fp32 out
// 8 warps = 2(m) x 4(n). Warp tile (BM/2) x (BN/4).
template<int EPI, int BM, int BN>
__device__ __forceinline__ void tgemm_body(
    int bxi, int byi,
    const __half* __restrict__ A, int lda,
    const __half* __restrict__ Bw, int ldbN,
    const float* __restrict__ bias,
    const float* __restrict__ Rres,
    void* __restrict__ Cv, int ldc,
    int K,
    const __half* __restrict__ B1, const __half* __restrict__ B2,
    const float* __restrict__ bias1, const float* __restrict__ bias2,
    float* __restrict__ C1, float* __restrict__ C2,
    char* dynraw)
{
    constexpr int MI  = BM / 32;
    constexpr int NT  = BN / 32;
    constexpr int WNS = BN / 4;
    constexpr int ST  = (BM == 64 && BN == 64) ? 4 : 3;
    constexpr int APH = 40;               // halfs per A row (32 + 8 pad)
    constexpr int BP2 = BN + 8;           // half2 per B kpair row
    constexpr int ASZ = BM * APH;         // halfs per stage
    constexpr int BSZ = 16 * BP2;         // half2 per stage
    __half*  As = (__half*)dynraw;
    __half2* Bs = (__half2*)(dynraw + ST * ASZ * 2);

    const int tid = threadIdx.x;
    const int lane = tid & 31, w = tid >> 5;
    const int wm = w & 1, wn = w >> 1;
    const int g = lane >> 2, t4 = lane & 3;
    int bx = bxi;
    const int m0 = byi * BM;

    const __half* Bp = Bw; const float* biasp = bias;
    float* Cf = (float*)Cv;
    __half* Ch = (__half*)Cv;
    if (EPI == 3) {
        int sel = bx / 6; bx -= sel * 6;
        Bp    = sel == 0 ? Bw   : (sel == 1 ? B1    : B2);
        biasp = sel == 0 ? bias : (sel == 1 ? bias1 : bias2);
        Cf    = sel == 0 ? Cf   : (sel == 1 ? C1    : C2);
    }
    const __half2* Bp2 = (const __half2*)Bp;
    const int n0 = bx * BN;

    float acc[MI][NT][4];
    #pragma unroll
    for (int i = 0; i < MI; i++)
        #pragma unroll
        for (int j = 0; j < NT; j++)
            #pragma unroll
            for (int q = 0; q < 4; q++) acc[i][j][q] = 0.f;

    auto loadA = [&](int kt, int st) {
        #pragma unroll
        for (int i = 0; i < BM / 64; i++) {
            int idx = tid + i * 256;
            int m = idx >> 2, c = (idx & 3) << 3;
            cp16(&As[st * ASZ + m * APH + c], A + (size_t)(m0 + m) * lda + kt + c);
        }
    };
    auto loadB = [&](int kt, int st) {
        const int kp0 = kt >> 1;
        if (BN == 128) {
            #pragma unroll
            for (int i = 0; i < 2; i++) {
                int idx = tid + i * 256;
                int kp = idx >> 5, q = (idx & 31) << 2;
                cp16(&Bs[st * BSZ + kp * BP2 + q],
                     Bp2 + (size_t)(kp0 + kp) * ldbN + n0 + q);
            }
        } else {
            int kp = tid >> 4, q = (tid & 15) << 2;
            cp16(&Bs[st * BSZ + kp * BP2 + q],
                 Bp2 + (size_t)(kp0 + kp) * ldbN + n0 + q);
        }
    };
    const int lmRow = lane & 15;
    const int lmOff = (lane >> 4) << 3;    // 0 or 8 halfs
    auto ldA = [&](int st, int kk, unsigned (&aF)[MI][4]) {
        #pragma unroll
        for (int i = 0; i < MI; i++) {
            int mb0 = wm * (MI * 16) + i * 16;
            unsigned addr = smem_u32(
                &As[st * ASZ + (mb0 + lmRow) * APH + kk * 16 + lmOff]);
            ldmatrix_x4(aF[i][0], aF[i][1], aF[i][2], aF[i][3], addr);
        }
    };
    auto ldB = [&](int st, int kk, unsigned (&bF)[NT][2]) {
        #pragma unroll
        for (int j = 0; j < NT; j++) {
            int nb = wn * WNS + j * 8 + g;
            bF[j][0] = *(const unsigned*)&Bs[st * BSZ + (kk * 8 + t4) * BP2 + nb];
            bF[j][1] = *(const unsigned*)&Bs[st * BSZ + (kk * 8 + t4 + 4) * BP2 + nb];
        }
    };
    auto compute = [&](int st) {
        unsigned aF[MI][4];
        unsigned bF[2][NT][2];
        ldB(st, 0, bF[0]);
        #pragma unroll
        for (int kk = 0; kk < 2; kk++) {
            ldA(st, kk, aF);
            if (kk == 0) ldB(st, 1, bF[1]);
            #pragma unroll
            for (int i = 0; i < MI; i++)
                #pragma unroll
                for (int j = 0; j < NT; j++)
                    mma_f16(acc[i][j], aF[i], bF[kk][j]);
        }
    };

    const int nt = K >> 5;
    loadA(0, 0); loadB(0, 0); cp_commit();
    if (nt > 1) { loadA(32, 1); loadB(32, 1); cp_commit(); }
    if (ST == 4 && nt > 2) { loadA(64, 2); loadB(64, 2); cp_commit(); }
    for (int t = 0; t < nt; t++) {
        if (t + ST - 1 < nt)                 cp_wait<ST - 2>();
        else if (ST == 4 && t + 2 < nt)      cp_wait<1>();
        else                                 cp_wait<0>();
        __syncthreads();
        compute(t % ST);
        if (t + ST - 1 < nt) {
            int st = (t + ST - 1) % ST;
            loadA((t + ST - 1) << 5, st);
            loadB((t + ST - 1) << 5, st);
            cp_commit();
        }
    }

    auto epi = [&](int row, int col, float2 v) {
        float2 bb = *(const float2*)(biasp + col);
        v.x += bb.x; v.y += bb.y;
        if (EPI == 1) {
            v.x = fmaxf(v.x, 0.f); v.y = fmaxf(v.y, 0.f);
            *(__half2*)(Ch + (size_t)row * ldc + col) = __floats2half2_rn(v.x, v.y);
            return;
        }
        if (EPI == 2) {
            float2 r = *(const float2*)(Rres + (size_t)row * ldc + col);
            v.x += r.x; v.y += r.y;
            *(float2*)(Cf + (size_t)row * ldc + col) = v;
            return;
        }
        // EPI 3: scatter to (b,h,l,d)
        int h = col >> 6, d = col & 63;
        float* dst = Cf + ((((size_t)(row >> 10) * NH + h) * LL + (row & 1023)) * DKK + d);
        *(float2*)dst = v;
    };

    #pragma unroll
    for (int i = 0; i < MI; i++) {
        int r0 = m0 + wm * (MI * 16) + i * 16 + g;
        #pragma unroll
        for (int j = 0; j < NT; j++) {
            int col = n0 + wn * WNS + j * 8 + t4 * 2;
            epi(r0,     col, make_float2(acc[i][j][0], acc[i][j][1]));
            epi(r0 + 8, col, make_float2(acc[i][j][2], acc[i][j][3]));
        }
    }
}

#define TGH_SMEM(BM, BN) ((((BM) == 64 && (BN) == 64) ? 4 : 3) * ((BM) * 40 * 2 + 16 * ((BN) + 8) * 4))

template<int EPI, int BM, int BN>
__global__ __launch_bounds__(256, (BM == 64 && BN == 64) ? 3 : 2) void tgemm(
    const __half* __restrict__ A, int lda,
    const __half* __restrict__ Bw, int ldbN,
    const float* __restrict__ bias,
    const float* __restrict__ Rres,
    void* __restrict__ Cv, int ldc,
    int K,
    const __half* __restrict__ B1, const __half* __restrict__ B2,
    const float* __restrict__ bias1, const float* __restrict__ bias2,
    float* __restrict__ C1, float* __restrict__ C2)
{
    extern __shared__ char dynraw[];
    tgemm_body<EPI, BM, BN>(blockIdx.x, blockIdx.y, A, lda, Bw, ldbN, bias, Rres,
                            Cv, ldc, K, B1, B2, bias1, bias2, C1, C2, dynraw);
}

// ---------------- posbias body (unchanged, fp32/tf32) ----------------
__device__ __forceinline__ void posbias_body(
    int kx, int qy, int b,
    const float* __restrict__ sx, const float* __restrict__ sy,
    const float* __restrict__ P1, const float* __restrict__ pb1,
    const float* __restrict__ P2, const float* __restrict__ pb2,
    float* __restrict__ S, float* dynsm)
{
    constexpr int HSTR = 260;
    constexpr int PSTR = 20;
    float* Hs   = dynsm;
    float* Ps   = Hs + 16 * HSTR * 2;
    float* sP1  = Ps + 16 * PSTR * 2;
    float* sPb1 = sP1 + 64;
    float* sPb2 = sPb1 + 32;
    float* qx   = sPb2 + 16;
    float* qy_  = qx + 16;
    float* kxp  = qy_ + 16;
    float* kyp  = kxp + 16;

    const int q0 = qy * 16, k0 = kx * 16;
    const int tid = threadIdx.x;
    const int lane = tid & 31, w = tid >> 5;
    const int g = lane >> 2, t4 = lane & 3;

    if (tid < 64) sP1[tid] = P1[tid];
    if (tid < 32) sPb1[tid] = pb1[tid];
    if (tid < 16) {
        sPb2[tid] = tid < NH ? pb2[tid] : 0.f;
        qx[tid]  = sx[b*LL + q0 + tid];
        qy_[tid] = sy[b*LL + q0 + tid];
        kxp[tid] = sx[b*LL + k0 + tid];
        kyp[tid] = sy[b*LL + k0 + tid];
    }
    #pragma unroll
    for (int ii = 0; ii < 2; ii++) {
        int v = tid + ii * 256;
        int n = v & 15, k = v >> 4;
        float val = (n < NH) ? P2[k * NH + n] : 0.f;
        int kk = k >> 3, hh = (k >> 2) & 1, cc = k & 3;
        Ps[((kk * 4 + cc) * PSTR + n) * 2 + hh] = val;
    }
    __syncthreads();

    {
        int qq = tid >> 4, kq = tid & 15;
        float rx = fminf(fmaxf(qx[qq] - kxp[kq], -1000.f), 1000.f) * 0.001f;
        float ry = fminf(fmaxf(qy_[qq] - kyp[kq], -1000.f), 1000.f) * 0.001f;
        #pragma unroll
        for (int kk = 0; kk < 4; kk++)
            #pragma unroll
            for (int cc = 0; cc < 4; cc++) {
                int j0 = kk * 8 + cc, j1 = j0 + 4;
                float h0 = fmaxf(fmaf(rx, sP1[j0], fmaf(ry, sP1[32+j0], sPb1[j0])), 0.f);
                float h1 = fmaxf(fmaf(rx, sP1[j1], fmaf(ry, sP1[32+j1], sPb1[j1])), 0.f);
                *(float2*)(&Hs[((kk * 4 + cc) * HSTR + tid) * 2]) = make_float2(h0, h1);
            }
    }
    __syncthreads();

    float acc[2][2][4];
    #pragma unroll
    for (int i = 0; i < 2; i++)
        #pragma unroll
        for (int j = 0; j < 2; j++)
            #pragma unroll
            for (int q = 0; q < 4; q++) acc[i][j][q] = 0.f;

    #pragma unroll
    for (int ks = 0; ks < 4; ks++) {
        unsigned aF[2][4];
        #pragma unroll
        for (int i = 0; i < 2; i++) {
            int mb = (w * 2 + i) * 16 + g;
            float2 lo = *(const float2*)(&Hs[((ks * 4 + t4) * HSTR + mb) * 2]);
            float2 hi = *(const float2*)(&Hs[((ks * 4 + t4) * HSTR + mb + 8) * 2]);
            aF[i][0] = __float_as_uint(lo.x); aF[i][1] = __float_as_uint(hi.x);
            aF[i][2] = __float_as_uint(lo.y); aF[i][3] = __float_as_uint(hi.y);
        }
        unsigned bF[2][2];
        #pragma unroll
        for (int j = 0; j < 2; j++) {
            float2 bb = *(const float2*)(&Ps[((ks * 4 + t4) * PSTR + j * 8 + g) * 2]);
            bF[j][0] = __float_as_uint(bb.x); bF[j][1] = __float_as_uint(bb.y);
        }
        #pragma unroll
        for (int i = 0; i < 2; i++)
            #pragma unroll
            for (int j = 0; j < 2; j++)
                mma_tf32(acc[i][j], aF[i], bF[j]);
    }

    #pragma unroll
    for (int i = 0; i < 2; i++) {
        int p0 = (w * 2 + i) * 16 + g;
        int p1 = p0 + 8;
        int q_0 = q0 + (p0 >> 4), k_0 = k0 + (p0 & 15);
        int q_1 = q0 + (p1 >> 4), k_1 = k0 + (p1 & 15);
        #pragma unroll
        for (int j = 0; j < 2; j++) {
            int c0 = j * 8 + t4 * 2, c1 = c0 + 1;
            if (c0 < NH) {
                S[((size_t)(b*NH + c0) * LL + q_0) * LL + k_0] = acc[i][j][0] + sPb2[c0];
                S[((size_t)(b*NH + c0) * LL + q_1) * LL + k_1] = acc[i][j][2] + sPb2[c0];
            }
            if (c1 < NH) {
                S[((size_t)(b*NH + c1) * LL + q_0) * LL + k_0] = acc[i][j][1] + sPb2[c1];
                S[((size_t)(b*NH + c1) * LL + q_1) * LL + k_1] = acc[i][j][3] + sPb2[c1];
            }
        }
    }
}

// ---------------- fused posbias + QKV (heterogeneous grid) ----------------
#define QKV_BLOCKS 288
#define PBQKV_GRID (QKV_BLOCKS + 64*64*BB)

__global__ __launch_bounds__(256, 2) void pbqkv_kernel(
    const __half* __restrict__ srcH,
    const __half* __restrict__ WqH, const float* __restrict__ bq,
    const __half* __restrict__ WkH, const float* __restrict__ bk,
    const __half* __restrict__ WvH, const float* __restrict__ bv,
    float* __restrict__ Q, float* __restrict__ Kq, float* __restrict__ V,
    const float* __restrict__ sx, const float* __restrict__ sy,
    const float* __restrict__ P1, const float* __restrict__ pb1,
    const float* __restrict__ P2, const float* __restrict__ pb2,
    float* __restrict__ S)
{
    extern __shared__ char dynraw[];
    const int bid = blockIdx.x;
    if (bid < QKV_BLOCKS) {
        tgemm_body<3, 128, 128>(bid % 18, bid / 18,
            srcH, DM, WqH, DM, bq, nullptr, Q, 0, DM,
            WkH, WvH, bk, bv, Kq, V, dynraw);
    } else {
        int p = bid - QKV_BLOCKS;
        posbias_body(p & 63, (p >> 6) & 63, p >> 12,
                     sx, sy, P1, pb1, P2, pb2, S, (float*)dynraw);
    }
}

// ---------------- flash64: QK^T + bias + online softmax + PV -----------------
#define FQSTR 68
struct Flash64Smem {
    float Qs[32*FQSTR*2];
    float Ss[32*FQSTR*2];
    float Ks[64*FQSTR];
    float Vs[64*FQSTR];
    float rowScale[64];
    float rowInv[64];
};
#define FL64_SMEM_BYTES sizeof(Flash64Smem)

__global__ __launch_bounds__(256, 3) void flash64_kernel(
    const float* __restrict__ S, const float* __restrict__ Q,
    const float* __restrict__ K, const float* __restrict__ V,
    __half* __restrict__ Oh)
{
    extern __shared__ char smraw[];
    Flash64Smem& sm = *reinterpret_cast<Flash64Smem*>(smraw);

    const int tid = threadIdx.x;
    const int lane = tid & 31, w = tid >> 5;
    const int wm = w & 1, wn = w >> 1;
    const int g = lane >> 2, t4 = lane & 3;
    const int bh = blockIdx.y, b = bh / NH, h = bh % NH;
    const int q0 = blockIdx.x * 64;

    const float* Qp = Q + ((size_t)bh * LL + q0) * DKK;
    const float* Kp = K + (size_t)bh * LL * DKK;
    const float* Vp = V + (size_t)bh * LL * DKK;
    const float* Sb = S + ((size_t)bh * LL + q0) * LL;

    auto loadK = [&](int t) {
        #pragma unroll
        for (int i = 0; i < 4; i++) {
            int idx = tid + i * 256;
            int r = idx >> 4, d4 = (idx & 15) << 2;
            cp16(&sm.Ks[r * FQSTR + d4], Kp + (size_t)(t * 64 + r) * DKK + d4);
        }
        cp_commit();
    };
    auto loadV = [&](int t) {
        #pragma unroll
        for (int i = 0; i < 4; i++) {
            int idx = tid + i * 256;
            int r = idx >> 4, d4 = (idx & 15) << 2;
            cp16(&sm.Vs[r * FQSTR + d4], Vp + (size_t)(t * 64 + r) * DKK + d4);
        }
        cp_commit();
    };

    loadK(0);
    loadV(0);

    #pragma unroll
    for (int i = 0; i < 4; i++) {
        int idx = tid + i * 256;
        int r = idx >> 4, d4 = (idx & 15) << 2;
        float4 v = *(const float4*)(Qp + (size_t)r * DKK + d4);
        int kk = d4 >> 3, hh = (d4 >> 2) & 1;
        float* p = sm.Qs + ((kk * 4) * FQSTR + r) * 2 + hh;
        p[0]          = tf32f(v.x * 0.125f);
        p[FQSTR*2]    = tf32f(v.y * 0.125f);
        p[FQSTR*4]    = tf32f(v.z * 0.125f);
        p[FQSTR*6]    = tf32f(v.w * 0.125f);
    }

    float accO[2][2][4];
    #pragma unroll
    for (int i = 0; i < 2; i++)
        #pragma unroll
        for (int j = 0; j < 2; j++)
            #pragma unroll
            for (int q = 0; q < 4; q++) accO[i][j][q] = 0.f;

    float rowM = -1e30f, rowL = 0.f;
    const int myrow = tid >> 2, quarter = tid & 3;

    for (int t = 0; t < 16; t++) {
        float accS[2][2][4];
        const int kb = t * 64;
        #pragma unroll
        for (int i = 0; i < 2; i++) {
            int r = wm * 32 + i * 16 + g;
            #pragma unroll
            for (int j = 0; j < 2; j++) {
                int col = kb + wn * 16 + j * 8 + t4 * 2;
                float2 b0 = *(const float2*)(Sb + (size_t)r * LL + col);
                float2 b1 = *(const float2*)(Sb + (size_t)(r + 8) * LL + col);
                accS[i][j][0] = b0.x; accS[i][j][1] = b0.y;
                accS[i][j][2] = b1.x; accS[i][j][3] = b1.y;
            }
        }

        cp_wait<1>();
        __syncthreads();

        #pragma unroll
        for (int ks = 0; ks < 8; ks++) {
            const int kc = ks * 8 + t4;
            unsigned aF[2][4];
            #pragma unroll
            for (int i = 0; i < 2; i++) {
                int mb = wm * 32 + i * 16 + g;
                float2 lo = *(const float2*)(sm.Qs + ((ks * 4 + t4) * FQSTR + mb) * 2);
                float2 hi = *(const float2*)(sm.Qs + ((ks * 4 + t4) * FQSTR + mb + 8) * 2);
                aF[i][0] = __float_as_uint(lo.x); aF[i][1] = __float_as_uint(hi.x);
                aF[i][2] = __float_as_uint(lo.y); aF[i][3] = __float_as_uint(hi.y);
            }
            unsigned bF[2][2];
            #pragma unroll
            for (int j = 0; j < 2; j++) {
                int nb = wn * 16 + j * 8 + g;
                bF[j][0] = __float_as_uint(sm.Ks[nb * FQSTR + kc]);
                bF[j][1] = __float_as_uint(sm.Ks[nb * FQSTR + kc + 4]);
            }
            #pragma unroll
            for (int i = 0; i < 2; i++)
                #pragma unroll
                for (int j = 0; j < 2; j++)
                    mma_tf32(accS[i][j], aF[i], bF[j]);
        }

        {
            const int cc = (t4 & 1) * 2, hh = t4 >> 1;
            #pragma unroll
            for (int i = 0; i < 2; i++) {
                int r = wm * 32 + i * 16 + g;
                #pragma unroll
                for (int j = 0; j < 2; j++) {
                    int colk = (wn * 16 + j * 8 + t4 * 2) >> 3;
                    int e = (colk * 4 + cc) * FQSTR + r;
                    sm.Ss[e * 2 + hh]                 = accS[i][j][0];
                    sm.Ss[(e + FQSTR) * 2 + hh]       = accS[i][j][1];
                    sm.Ss[(e + 8) * 2 + hh]           = accS[i][j][2];
                    sm.Ss[(e + FQSTR + 8) * 2 + hh]   = accS[i][j][3];
                }
            }
        }
        __syncthreads();
        if (t + 1 < 16) loadK(t + 1);

        {
            float2 vals[8];
            float mx = -1e30f;
            #pragma unroll
            for (int e = 0; e < 8; e++) {
                int kk = 2 * quarter + (e >> 2), cc2 = e & 3;
                vals[e] = *(const float2*)(sm.Ss + ((kk * 4 + cc2) * FQSTR + myrow) * 2);
                mx = fmaxf(mx, fmaxf(vals[e].x, vals[e].y));
            }
            mx = fmaxf(mx, __shfl_xor_sync(0xffffffffu, mx, 1));
            mx = fmaxf(mx, __shfl_xor_sync(0xffffffffu, mx, 2));
            float mNew = fmaxf(rowM, mx);
            float scale = __expf(rowM - mNew);
            float sum = 0.f;
            #pragma unroll
            for (int e = 0; e < 8; e++) {
                vals[e].x = __expf(vals[e].x - mNew);
                vals[e].y = __expf(vals[e].y - mNew);
                sum += vals[e].x + vals[e].y;
                int kk = 2 * quarter + (e >> 2), cc2 = e & 3;
                *(float2*)(sm.Ss + ((kk * 4 + cc2) * FQSTR + myrow) * 2) =
                    make_float2(vals[e].x, vals[e].y);
            }
            sum += __shfl_xor_sync(0xffffffffu, sum, 1);
            sum += __shfl_xor_sync(0xffffffffu, sum, 2);
            rowL = rowL * scale + sum;
            rowM = mNew;
            if (quarter == 0) sm.rowScale[myrow] = scale;
        }
        if (t + 1 < 16) cp_wait<1>(); else cp_wait<0>();
        __syncthreads();

        #pragma unroll
        for (int i = 0; i < 2; i++) {
            int r = wm * 32 + i * 16 + g;
            float s0 = sm.rowScale[r], s1 = sm.rowScale[r + 8];
            #pragma unroll
            for (int j = 0; j < 2; j++) {
                accO[i][j][0] *= s0; accO[i][j][1] *= s0;
                accO[i][j][2] *= s1; accO[i][j][3] *= s1;
            }
        }

        #pragma unroll
        for (int ks = 0; ks < 8; ks++) {
            const int kc = ks * 8 + t4;
            unsigned aF[2][4];
            #pragma unroll
            for (int i = 0; i < 2; i++) {
                int mb = wm * 32 + i * 16 + g;
                float2 lo = *(const float2*)(sm.Ss + ((ks * 4 + t4) * FQSTR + mb) * 2);
                float2 hi = *(const float2*)(sm.Ss + ((ks * 4 + t4) * FQSTR + mb + 8) * 2);
                aF[i][0] = __float_as_uint(lo.x); aF[i][1] = __float_as_uint(hi.x);
                aF[i][2] = __float_as_uint(lo.y); aF[i][3] = __float_as_uint(hi.y);
            }
            unsigned bF[2][2];
            #pragma unroll
            for (int j = 0; j < 2; j++) {
                int nb = wn * 16 + j * 8 + g;
                bF[j][0] = __float_as_uint(sm.Vs[kc * FQSTR + nb]);
                bF[j][1] = __float_as_uint(sm.Vs[(kc + 4) * FQSTR + nb]);
            }
            #pragma unroll
            for (int i = 0; i < 2; i++)
                #pragma unroll
                for (int j = 0; j < 2; j++)
                    mma_tf32(accO[i][j], aF[i], bF[j]);
        }
        __syncthreads();
        if (t + 1 < 16) loadV(t + 1);
    }

    if (quarter == 0) sm.rowInv[myrow] = 1.f / rowL;
    __syncthreads();

    __half* Op = Oh + ((size_t)b * LL + q0) * DM + h * DKK;
    #pragma unroll
    for (int i = 0; i < 2; i++) {
        int r = wm * 32 + i * 16 + g;
        float i0 = sm.rowInv[r], i1 = sm.rowInv[r + 8];
        #pragma unroll
        for (int j = 0; j < 2; j++) {
            int col = wn * 16 + j * 8 + t4 * 2;
            *(__half2*)(Op + (size_t)r * DM + col) =
                __floats2half2_rn(accO[i][j][0] * i0, accO[i][j][1] * i0);
            *(__half2*)(Op + (size_t)(r + 8) * DM + col) =
                __floats2half2_rn(accO[i][j][2] * i1, accO[i][j][3] * i1);
        }
    }
}

// ---------------- layernorm (warp-shuffle), optional fp16 secondary output ----------
__global__ __launch_bounds__(256) void layernorm_kernel(
    const float* __restrict__ X, const float* __restrict__ g, const float* __restrict__ be,
    float* __restrict__ Y, __half* __restrict__ Yh)
{
    __shared__ float redS[8], redQ[8];
    const size_t row = blockIdx.x;
    const float* p = X + row * DM;
    const int tid = threadIdx.x;
    const int lane = tid & 31, w = tid >> 5;
    float v[3];
    float s = 0.f, q = 0.f;
    #pragma unroll
    for (int i = 0; i < 3; i++) {
        v[i] = p[tid + i*256];
        s += v[i];
        q = fmaf(v[i], v[i], q);
    }
    #pragma unroll
    for (int d = 16; d > 0; d >>= 1) {
        s += __shfl_xor_sync(0xffffffffu, s, d);
        q += __shfl_xor_sync(0xffffffffu, q, d);
    }
    if (lane == 0) { redS[w] = s; redQ[w] = q; }
    __syncthreads();
    {
        float s8 = redS[lane & 7], q8 = redQ[lane & 7];
        #pragma unroll
        for (int d = 4; d > 0; d >>= 1) {
            s8 += __shfl_xor_sync(0xffffffffu, s8, d);
            q8 += __shfl_xor_sync(0xffffffffu, q8, d);
        }
        s = s8; q = q8;
    }
    float mean = s * (1.f/DM);
    float var  = q * (1.f/DM) - mean * mean;
    float rstd = rsqrtf(var + 1e-5f);
    #pragma unroll
    for (int i = 0; i < 3; i++) {
        int c = tid + i*256;
        float o = (v[i] - mean) * rstd * g[c] + be[c];
        Y[row * DM + c] = o;
        if (Yh) Yh[row * DM + c] = __float2half(o);
    }
}

// ---------------- launch ----------------
extern "C" void kernel_launch(void* const* d_in, const int* in_sizes, int n_in,
                              void* d_out, int out_size)
{
    const float* src = (const float*)d_in[0];
    const float* sx  = (const float*)d_in[1];
    const float* sy  = (const float*)d_in[2];
    const float* Wq  = (const float*)d_in[3];  const float* bq  = (const float*)d_in[4];
    const float* Wk  = (const float*)d_in[5];  const float* bk  = (const float*)d_in[6];
    const float* Wv  = (const float*)d_in[7];  const float* bv  = (const float*)d_in[8];
    const float* Wo  = (const float*)d_in[9];  const float* bo  = (const float*)d_in[10];
    const float* P1  = (const float*)d_in[11]; const float* pb1 = (const float*)d_in[12];
    const float* P2  = (const float*)d_in[13]; const float* pb2 = (const float*)d_in[14];
    const float* W1  = (const float*)d_in[15]; const float* b1  = (const float*)d_in[16];
    const float* W2  = (const float*)d_in[17]; const float* b2  = (const float*)d_in[18];
    const float* g1  = (const float*)d_in[19]; const float* be1 = (const float*)d_in[20];
    const float* g2  = (const float*)d_in[21]; const float* be2 = (const float*)d_in[22];
    float* out = (float*)d_out;

    float *Q, *K, *V, *S, *Xres, *X1;
    __half *srcH, *WqH, *WkH, *WvH, *WoH, *W1H, *W2H, *OH, *X1H, *H1H;
    cudaGetSymbolAddress((void**)&Q,    g_Q);
    cudaGetSymbolAddress((void**)&K,    g_K);
    cudaGetSymbolAddress((void**)&V,    g_V);
    cudaGetSymbolAddress((void**)&S,    g_S);
    cudaGetSymbolAddress((void**)&Xres, g_Xres);
    cudaGetSymbolAddress((void**)&X1,   g_X1);
    cudaGetSymbolAddress((void**)&srcH, g_srcH);
    cudaGetSymbolAddress((void**)&WqH,  g_WqH);
    cudaGetSymbolAddress((void**)&WkH,  g_WkH);
    cudaGetSymbolAddress((void**)&WvH,  g_WvH);
    cudaGetSymbolAddress((void**)&WoH,  g_WoH);
    cudaGetSymbolAddress((void**)&W1H,  g_W1H);
    cudaGetSymbolAddress((void**)&W2H,  g_W2H);
    cudaGetSymbolAddress((void**)&OH,   g_OH);
    cudaGetSymbolAddress((void**)&X1H,  g_X1H);
    cudaGetSymbolAddress((void**)&H1H,  g_H1H);

    cudaFuncSetAttribute(flash64_kernel, cudaFuncAttributeMaxDynamicSharedMemorySize,
                         (int)FL64_SMEM_BYTES);
    cudaFuncSetAttribute(pbqkv_kernel, cudaFuncAttributeMaxDynamicSharedMemorySize,
                         TGH_SMEM(128, 128));
    cudaFuncSetAttribute(tgemm<1, 128, 128>, cudaFuncAttributeMaxDynamicSharedMemorySize,
                         TGH_SMEM(128, 128));
    cudaFuncSetAttribute(tgemm<2, 64, 64>, cudaFuncAttributeMaxDynamicSharedMemorySize,
                         TGH_SMEM(64, 64));

    // 0) convert src + weights to fp16 (weights k-pair-interleaved)
    prep_kernel<<<PREP_GRID, 256>>>(src, Wq, Wk, Wv, Wo, W1, W2,
                                    srcH, WqH, WkH, WvH, WoH, W1H, W2H);

    // 1) fused: relative-position bias -> S  ||  QKV projections -> Q,K,V
    pbqkv_kernel<<<PBQKV_GRID, 256, TGH_SMEM(128, 128)>>>(
        srcH, WqH, bq, WkH, bk, WvH, bv, Q, K, V,
        sx, sy, P1, pb1, P2, pb2, S);

    // 2) flash attention: softmax(QK^T/8 + bias) @ V -> O (fp16)
    flash64_kernel<<<dim3(LL/64, BB*NH), 256, FL64_SMEM_BYTES>>>(S, Q, K, V, OH);

    // 3) Xres = src + O @ Wo + bo ; LN1 -> X1 (fp32 + fp16)
    tgemm<2, 64, 64><<<dim3(DM/64, ROWS/64, 1), 256, TGH_SMEM(64, 64)>>>(
        OH, DM, WoH, DM, bo, src, Xres, DM, DM,
        nullptr, nullptr, nullptr, nullptr, nullptr, nullptr);
    layernorm_kernel<<<ROWS, 256>>>(Xres, g1, be1, X1, X1H);

    // 4) FFN: H1 = relu(X1 @ W1 + b1) (fp16) ; Xres = X1 + H1 @ W2 + b2
    tgemm<1, 128, 128><<<dim3(FFD/128, ROWS/128, 1), 256, TGH_SMEM(128, 128)>>>(
        X1H, DM, W1H, FFD, b1, nullptr, H1H, FFD, DM,
        nullptr, nullptr, nullptr, nullptr, nullptr, nullptr);
    tgemm<2, 64, 64><<<dim3(DM/64, ROWS/64, 1), 256, TGH_SMEM(64, 64)>>>(
        H1H, FFD, W2H, DM, b2, X1, Xres, DM, FFD,
        nullptr, nullptr, nullptr, nullptr, nullptr, nullptr);

    // 5) LN2 -> output
    layernorm_kernel<<<ROWS, 256>>>(Xres, g2, be2, out, nullptr);
}

// round 17
// speedup vs baseline: 1.5601x; 1.1976x over previous
#include <cuda_runtime.h>
#include <cuda_fp16.h>
#include <math.h>

#define BB 2
#define LL 1024
#define DM 768
#define NH 12
#define DKK 64
#define FFD 3072
#define PH 32
#define ROWS (BB*LL)

// ---------------- scratch ----------------
__device__ float g_S[(size_t)BB*NH*LL*LL];
__device__ float g_Xres[BB*LL*DM];
__device__ float g_X1[BB*LL*DM];
__device__ __half g_QH[BB*NH*LL*DKK];
__device__ __half g_KH[BB*NH*LL*DKK];
__device__ __half g_VH[BB*NH*LL*DKK];   // k-pair interleaved [bh][l/2][d][l&1]
__device__ __half g_srcH[ROWS*DM];
__device__ __half g_WqH[DM*DM];
__device__ __half g_WkH[DM*DM];
__device__ __half g_WvH[DM*DM];
__device__ __half g_WoH[DM*DM];
__device__ __half g_W1H[DM*FFD];
__device__ __half g_W2H[FFD*DM];
__device__ __half g_OH[ROWS*DM];
__device__ __half g_X1H[ROWS*DM];
__device__ __half g_H1H[(size_t)ROWS*FFD];

// ---------------- helpers ----------------
__device__ __forceinline__ void mma_tf32(float* c, const unsigned* a, const unsigned* b) {
    asm volatile(
        "mma.sync.aligned.m16n8k8.row.col.f32.tf32.tf32.f32 "
        "{%0,%1,%2,%3}, {%4,%5,%6,%7}, {%8,%9}, {%0,%1,%2,%3};"
        : "+f"(c[0]), "+f"(c[1]), "+f"(c[2]), "+f"(c[3])
        : "r"(a[0]), "r"(a[1]), "r"(a[2]), "r"(a[3]), "r"(b[0]), "r"(b[1]));
}

__device__ __forceinline__ void mma_f16(float* c, const unsigned* a, const unsigned* b) {
    asm volatile(
        "mma.sync.aligned.m16n8k16.row.col.f32.f16.f16.f32 "
        "{%0,%1,%2,%3}, {%4,%5,%6,%7}, {%8,%9}, {%0,%1,%2,%3};"
        : "+f"(c[0]), "+f"(c[1]), "+f"(c[2]), "+f"(c[3])
        : "r"(a[0]), "r"(a[1]), "r"(a[2]), "r"(a[3]), "r"(b[0]), "r"(b[1]));
}

__device__ __forceinline__ void ldmatrix_x4(unsigned& r0, unsigned& r1,
                                            unsigned& r2, unsigned& r3, unsigned addr) {
    asm volatile("ldmatrix.sync.aligned.m8n8.x4.shared.b16 {%0,%1,%2,%3}, [%4];"
        : "=r"(r0), "=r"(r1), "=r"(r2), "=r"(r3) : "r"(addr));
}

__device__ __forceinline__ unsigned smem_u32(const void* p) {
    return (unsigned)__cvta_generic_to_shared(p);
}

__device__ __forceinline__ void cp16(void* dst_smem, const void* src) {
    unsigned d = (unsigned)__cvta_generic_to_shared(dst_smem);
    asm volatile("cp.async.cg.shared.global [%0], [%1], 16;" :: "r"(d), "l"(src));
}
__device__ __forceinline__ void cp_commit() { asm volatile("cp.async.commit_group;"); }
template<int N> __device__ __forceinline__ void cp_wait() {
    asm volatile("cp.async.wait_group %0;" :: "n"(N));
}

// ---------------- prep: fp32 -> fp16 conversions ----------------
#define PREP_GRID 4224
__global__ __launch_bounds__(256) void prep_kernel(
    const float* __restrict__ src,
    const float* __restrict__ Wq, const float* __restrict__ Wk,
    const float* __restrict__ Wv, const float* __restrict__ Wo,
    const float* __restrict__ W1, const float* __restrict__ W2,
    __half* __restrict__ srcH,
    __half* __restrict__ WqH, __half* __restrict__ WkH,
    __half* __restrict__ WvH, __half* __restrict__ WoH,
    __half* __restrict__ W1H, __half* __restrict__ W2H)
{
    int bid = blockIdx.x;
    if (bid < 768) {
        int base = bid * 2048;
        for (int i = threadIdx.x; i < 2048; i += 256)
            srcH[base + i] = __float2half(src[base + i]);
        return;
    }
    bid -= 768;
    const float* W; __half* Wh; int N;
    if      (bid < 288)  { W = Wq; Wh = WqH; N = 768; }
    else if (bid < 576)  { W = Wk; Wh = WkH; N = 768;  bid -= 288; }
    else if (bid < 864)  { W = Wv; Wh = WvH; N = 768;  bid -= 576; }
    else if (bid < 1152) { W = Wo; Wh = WoH; N = 768;  bid -= 864; }
    else if (bid < 2304) { W = W1; Wh = W1H; N = 3072; bid -= 1152; }
    else                 { W = W2; Wh = W2H; N = 768;  bid -= 2304; }
    int base = bid * 2048;
    for (int i = threadIdx.x; i < 2048; i += 256) {
        int e = base + i;
        int k = e / N, n = e - k * N;
        Wh[(size_t)(k >> 1) * (2 * N) + n * 2 + (k & 1)] = __float2half(W[e]);
    }
}

// ---------------- fp16 tensor-core GEMM body: BK=32, m16n8k16 ----------------
// EPI 1: relu(+bias), fp16 out   2: +bias +R residual, fp32 out
//     3: fused QKV scatter -> fp16 (Q scaled 1/8; V pair-interleaved)
template<int EPI, int BM, int BN>
__device__ __forceinline__ void tgemm_body(
    int bxi, int byi,
    const __half* __restrict__ A, int lda,
    const __half* __restrict__ Bw, int ldbN,
    const float* __restrict__ bias,
    const float* __restrict__ Rres,
    void* __restrict__ Cv, int ldc,
    int K,
    const __half* __restrict__ B1, const __half* __restrict__ B2,
    const float* __restrict__ bias1, const float* __restrict__ bias2,
    __half* __restrict__ C1, __half* __restrict__ C2,
    char* dynraw)
{
    constexpr int MI  = BM / 32;
    constexpr int NT  = BN / 32;
    constexpr int WNS = BN / 4;
    constexpr int ST  = (BM == 64 && BN == 64) ? 4 : 3;
    constexpr int APH = 40;
    constexpr int BP2 = BN + 8;
    constexpr int ASZ = BM * APH;
    constexpr int BSZ = 16 * BP2;
    __half*  As = (__half*)dynraw;
    __half2* Bs = (__half2*)(dynraw + ST * ASZ * 2);

    const int tid = threadIdx.x;
    const int lane = tid & 31, w = tid >> 5;
    const int wm = w & 1, wn = w >> 1;
    const int g = lane >> 2, t4 = lane & 3;
    int bx = bxi;
    const int m0 = byi * BM;

    const __half* Bp = Bw; const float* biasp = bias;
    float* Cf = (float*)Cv;
    __half* Chsel = (__half*)Cv;
    int sel = 0;
    if (EPI == 3) {
        sel = bx / 6; bx -= sel * 6;
        Bp    = sel == 0 ? Bw   : (sel == 1 ? B1    : B2);
        biasp = sel == 0 ? bias : (sel == 1 ? bias1 : bias2);
        Chsel = sel == 0 ? Chsel : (sel == 1 ? C1 : C2);
    }
    const float qs = (EPI == 3 && sel == 0) ? 0.125f : 1.f;
    const __half2* Bp2 = (const __half2*)Bp;
    const int n0 = bx * BN;

    float acc[MI][NT][4];
    #pragma unroll
    for (int i = 0; i < MI; i++)
        #pragma unroll
        for (int j = 0; j < NT; j++)
            #pragma unroll
            for (int q = 0; q < 4; q++) acc[i][j][q] = 0.f;

    auto loadA = [&](int kt, int st) {
        #pragma unroll
        for (int i = 0; i < BM / 64; i++) {
            int idx = tid + i * 256;
            int m = idx >> 2, c = (idx & 3) << 3;
            cp16(&As[st * ASZ + m * APH + c], A + (size_t)(m0 + m) * lda + kt + c);
        }
    };
    auto loadB = [&](int kt, int st) {
        const int kp0 = kt >> 1;
        if (BN == 128) {
            #pragma unroll
            for (int i = 0; i < 2; i++) {
                int idx = tid + i * 256;
                int kp = idx >> 5, q = (idx & 31) << 2;
                cp16(&Bs[st * BSZ + kp * BP2 + q],
                     Bp2 + (size_t)(kp0 + kp) * ldbN + n0 + q);
            }
        } else {
            int kp = tid >> 4, q = (tid & 15) << 2;
            cp16(&Bs[st * BSZ + kp * BP2 + q],
                 Bp2 + (size_t)(kp0 + kp) * ldbN + n0 + q);
        }
    };
    const int lmRow = lane & 15;
    const int lmOff = (lane >> 4) << 3;
    auto ldA = [&](int st, int kk, unsigned (&aF)[MI][4]) {
        #pragma unroll
        for (int i = 0; i < MI; i++) {
            int mb0 = wm * (MI * 16) + i * 16;
            unsigned addr = smem_u32(
                &As[st * ASZ + (mb0 + lmRow) * APH + kk * 16 + lmOff]);
            ldmatrix_x4(aF[i][0], aF[i][1], aF[i][2], aF[i][3], addr);
        }
    };
    auto ldB = [&](int st, int kk, unsigned (&bF)[NT][2]) {
        #pragma unroll
        for (int j = 0; j < NT; j++) {
            int nb = wn * WNS + j * 8 + g;
            bF[j][0] = *(const unsigned*)&Bs[st * BSZ + (kk * 8 + t4) * BP2 + nb];
            bF[j][1] = *(const unsigned*)&Bs[st * BSZ + (kk * 8 + t4 + 4) * BP2 + nb];
        }
    };
    auto compute = [&](int st) {
        unsigned aF[MI][4];
        unsigned bF[2][NT][2];
        ldB(st, 0, bF[0]);
        #pragma unroll
        for (int kk = 0; kk < 2; kk++) {
            ldA(st, kk, aF);
            if (kk == 0) ldB(st, 1, bF[1]);
            #pragma unroll
            for (int i = 0; i < MI; i++)
                #pragma unroll
                for (int j = 0; j < NT; j++)
                    mma_f16(acc[i][j], aF[i], bF[kk][j]);
        }
    };

    const int nt = K >> 5;
    loadA(0, 0); loadB(0, 0); cp_commit();
    if (nt > 1) { loadA(32, 1); loadB(32, 1); cp_commit(); }
    if (ST == 4 && nt > 2) { loadA(64, 2); loadB(64, 2); cp_commit(); }
    for (int t = 0; t < nt; t++) {
        if (t + ST - 1 < nt)                 cp_wait<ST - 2>();
        else if (ST == 4 && t + 2 < nt)      cp_wait<1>();
        else                                 cp_wait<0>();
        __syncthreads();
        compute(t % ST);
        if (t + ST - 1 < nt) {
            int st = (t + ST - 1) % ST;
            loadA((t + ST - 1) << 5, st);
            loadB((t + ST - 1) << 5, st);
            cp_commit();
        }
    }

    auto epi = [&](int row, int col, float2 v) {
        float2 bb = *(const float2*)(biasp + col);
        v.x += bb.x; v.y += bb.y;
        if (EPI == 1) {
            v.x = fmaxf(v.x, 0.f); v.y = fmaxf(v.y, 0.f);
            *(__half2*)(Chsel + (size_t)row * ldc + col) = __floats2half2_rn(v.x, v.y);
            return;
        }
        if (EPI == 2) {
            float2 r = *(const float2*)(Rres + (size_t)row * ldc + col);
            v.x += r.x; v.y += r.y;
            *(float2*)(Cf + (size_t)row * ldc + col) = v;
            return;
        }
        // EPI 3: fp16 scatter
        v.x *= qs; v.y *= qs;
        int h = col >> 6, d = col & 63;
        size_t l = row & 1023;
        size_t bh = (size_t)(row >> 10) * NH + h;
        if (sel < 2) {
            *(__half2*)(Chsel + (bh * LL + l) * DKK + d) = __floats2half2_rn(v.x, v.y);
        } else {
            __half* dst = Chsel + ((bh * (LL/2) + (l >> 1)) * DKK + d) * 2 + (l & 1);
            dst[0] = __float2half(v.x);
            dst[2] = __float2half(v.y);
        }
    };

    #pragma unroll
    for (int i = 0; i < MI; i++) {
        int r0 = m0 + wm * (MI * 16) + i * 16 + g;
        #pragma unroll
        for (int j = 0; j < NT; j++) {
            int col = n0 + wn * WNS + j * 8 + t4 * 2;
            epi(r0,     col, make_float2(acc[i][j][0], acc[i][j][1]));
            epi(r0 + 8, col, make_float2(acc[i][j][2], acc[i][j][3]));
        }
    }
}

#define TGH_SMEM(BM, BN) ((((BM) == 64 && (BN) == 64) ? 4 : 3) * ((BM) * 40 * 2 + 16 * ((BN) + 8) * 4))

template<int EPI, int BM, int BN>
__global__ __launch_bounds__(256, (BM == 64 && BN == 64) ? 3 : 2) void tgemm(
    const __half* __restrict__ A, int lda,
    const __half* __restrict__ Bw, int ldbN,
    const float* __restrict__ bias,
    const float* __restrict__ Rres,
    void* __restrict__ Cv, int ldc,
    int K,
    const __half* __restrict__ B1, const __half* __restrict__ B2,
    const float* __restrict__ bias1, const float* __restrict__ bias2,
    __half* __restrict__ C1, __half* __restrict__ C2)
{
    extern __shared__ char dynraw[];
    tgemm_body<EPI, BM, BN>(blockIdx.x, blockIdx.y, A, lda, Bw, ldbN, bias, Rres,
                            Cv, ldc, K, B1, B2, bias1, bias2, C1, C2, dynraw);
}

// ---------------- posbias body (fp32/tf32, unchanged) ----------------
__device__ __forceinline__ void posbias_body(
    int kx, int qy, int b,
    const float* __restrict__ sx, const float* __restrict__ sy,
    const float* __restrict__ P1, const float* __restrict__ pb1,
    const float* __restrict__ P2, const float* __restrict__ pb2,
    float* __restrict__ S, float* dynsm)
{
    constexpr int HSTR = 260;
    constexpr int PSTR = 20;
    float* Hs   = dynsm;
    float* Ps   = Hs + 16 * HSTR * 2;
    float* sP1  = Ps + 16 * PSTR * 2;
    float* sPb1 = sP1 + 64;
    float* sPb2 = sPb1 + 32;
    float* qx   = sPb2 + 16;
    float* qy_  = qx + 16;
    float* kxp  = qy_ + 16;
    float* kyp  = kxp + 16;

    const int q0 = qy * 16, k0 = kx * 16;
    const int tid = threadIdx.x;
    const int lane = tid & 31, w = tid >> 5;
    const int g = lane >> 2, t4 = lane & 3;

    if (tid < 64) sP1[tid] = P1[tid];
    if (tid < 32) sPb1[tid] = pb1[tid];
    if (tid < 16) {
        sPb2[tid] = tid < NH ? pb2[tid] : 0.f;
        qx[tid]  = sx[b*LL + q0 + tid];
        qy_[tid] = sy[b*LL + q0 + tid];
        kxp[tid] = sx[b*LL + k0 + tid];
        kyp[tid] = sy[b*LL + k0 + tid];
    }
    #pragma unroll
    for (int ii = 0; ii < 2; ii++) {
        int v = tid + ii * 256;
        int n = v & 15, k = v >> 4;
        float val = (n < NH) ? P2[k * NH + n] : 0.f;
        int kk = k >> 3, hh = (k >> 2) & 1, cc = k & 3;
        Ps[((kk * 4 + cc) * PSTR + n) * 2 + hh] = val;
    }
    __syncthreads();

    {
        int qq = tid >> 4, kq = tid & 15;
        float rx = fminf(fmaxf(qx[qq] - kxp[kq], -1000.f), 1000.f) * 0.001f;
        float ry = fminf(fmaxf(qy_[qq] - kyp[kq], -1000.f), 1000.f) * 0.001f;
        #pragma unroll
        for (int kk = 0; kk < 4; kk++)
            #pragma unroll
            for (int cc = 0; cc < 4; cc++) {
                int j0 = kk * 8 + cc, j1 = j0 + 4;
                float h0 = fmaxf(fmaf(rx, sP1[j0], fmaf(ry, sP1[32+j0], sPb1[j0])), 0.f);
                float h1 = fmaxf(fmaf(rx, sP1[j1], fmaf(ry, sP1[32+j1], sPb1[j1])), 0.f);
                *(float2*)(&Hs[((kk * 4 + cc) * HSTR + tid) * 2]) = make_float2(h0, h1);
            }
    }
    __syncthreads();

    float acc[2][2][4];
    #pragma unroll
    for (int i = 0; i < 2; i++)
        #pragma unroll
        for (int j = 0; j < 2; j++)
            #pragma unroll
            for (int q = 0; q < 4; q++) acc[i][j][q] = 0.f;

    #pragma unroll
    for (int ks = 0; ks < 4; ks++) {
        unsigned aF[2][4];
        #pragma unroll
        for (int i = 0; i < 2; i++) {
            int mb = (w * 2 + i) * 16 + g;
            float2 lo = *(const float2*)(&Hs[((ks * 4 + t4) * HSTR + mb) * 2]);
            float2 hi = *(const float2*)(&Hs[((ks * 4 + t4) * HSTR + mb + 8) * 2]);
            aF[i][0] = __float_as_uint(lo.x); aF[i][1] = __float_as_uint(hi.x);
            aF[i][2] = __float_as_uint(lo.y); aF[i][3] = __float_as_uint(hi.y);
        }
        unsigned bF[2][2];
        #pragma unroll
        for (int j = 0; j < 2; j++) {
            float2 bb = *(const float2*)(&Ps[((ks * 4 + t4) * PSTR + j * 8 + g) * 2]);
            bF[j][0] = __float_as_uint(bb.x); bF[j][1] = __float_as_uint(bb.y);
        }
        #pragma unroll
        for (int i = 0; i < 2; i++)
            #pragma unroll
            for (int j = 0; j < 2; j++)
                mma_tf32(acc[i][j], aF[i], bF[j]);
    }

    #pragma unroll
    for (int i = 0; i < 2; i++) {
        int p0 = (w * 2 + i) * 16 + g;
        int p1 = p0 + 8;
        int q_0 = q0 + (p0 >> 4), k_0 = k0 + (p0 & 15);
        int q_1 = q0 + (p1 >> 4), k_1 = k0 + (p1 & 15);
        #pragma unroll
        for (int j = 0; j < 2; j++) {
            int c0 = j * 8 + t4 * 2, c1 = c0 + 1;
            if (c0 < NH) {
                S[((size_t)(b*NH + c0) * LL + q_0) * LL + k_0] = acc[i][j][0] + sPb2[c0];
                S[((size_t)(b*NH + c0) * LL + q_1) * LL + k_1] = acc[i][j][2] + sPb2[c0];
            }
            if (c1 < NH) {
                S[((size_t)(b*NH + c1) * LL + q_0) * LL + k_0] = acc[i][j][1] + sPb2[c1];
                S[((size_t)(b*NH + c1) * LL + q_1) * LL + k_1] = acc[i][j][3] + sPb2[c1];
            }
        }
    }
}

// ---------------- fused posbias + QKV (heterogeneous grid) ----------------
#define QKV_BLOCKS 288
#define PBQKV_GRID (QKV_BLOCKS + 64*64*BB)

__global__ __launch_bounds__(256, 2) void pbqkv_kernel(
    const __half* __restrict__ srcH,
    const __half* __restrict__ WqH, const float* __restrict__ bq,
    const __half* __restrict__ WkH, const float* __restrict__ bk,
    const __half* __restrict__ WvH, const float* __restrict__ bv,
    __half* __restrict__ Q, __half* __restrict__ Kq, __half* __restrict__ V,
    const float* __restrict__ sx, const float* __restrict__ sy,
    const float* __restrict__ P1, const float* __restrict__ pb1,
    const float* __restrict__ P2, const float* __restrict__ pb2,
    float* __restrict__ S)
{
    extern __shared__ char dynraw[];
    const int bid = blockIdx.x;
    if (bid < QKV_BLOCKS) {
        tgemm_body<3, 128, 128>(bid % 18, bid / 18,
            srcH, DM, WqH, DM, bq, nullptr, Q, 0, DM,
            WkH, WvH, bk, bv, Kq, V, dynraw);
    } else {
        int p = bid - QKV_BLOCKS;
        posbias_body(p & 63, (p >> 6) & 63, p >> 12,
                     sx, sy, P1, pb1, P2, pb2, S, (float*)dynraw);
    }
}

// ---------------- flash64 fp16: QK^T + bias + online softmax + PV -----------------
#define QPH 72
#define VPH 144
struct Flash64SmemH {
    __half Qs[64*QPH];
    __half Ss[64*QPH];
    __half Ks[64*QPH];
    __half Vs[32*VPH];
    float rowScale[64];
    float rowInv[64];
};
#define FLH_SMEM_BYTES sizeof(Flash64SmemH)

__global__ __launch_bounds__(256, 3) void flash64_kernel(
    const float* __restrict__ S, const __half* __restrict__ Q,
    const __half* __restrict__ K, const __half* __restrict__ V,
    __half* __restrict__ Oh)
{
    extern __shared__ char smraw[];
    Flash64SmemH& sm = *reinterpret_cast<Flash64SmemH*>(smraw);

    const int tid = threadIdx.x;
    const int lane = tid & 31, w = tid >> 5;
    const int wm = w & 1, wn = w >> 1;
    const int g = lane >> 2, t4 = lane & 3;
    const int bh = blockIdx.y, b = bh / NH, h = bh % NH;
    const int q0 = blockIdx.x * 64;

    const __half* Qp = Q + ((size_t)bh * LL + q0) * DKK;
    const __half* Kp = K + (size_t)bh * LL * DKK;
    const __half* Vp = V + (size_t)bh * LL * DKK;   // interleaved [kp][128]
    const float*  Sb = S + ((size_t)bh * LL + q0) * LL;

    auto loadK = [&](int t) {
        #pragma unroll
        for (int i = 0; i < 2; i++) {
            int idx = tid + i * 256;
            int r = idx >> 3, c = (idx & 7) << 3;
            cp16(&sm.Ks[r * QPH + c], Kp + (size_t)(t * 64 + r) * DKK + c);
        }
        cp_commit();
    };
    auto loadV = [&](int t) {
        #pragma unroll
        for (int i = 0; i < 2; i++) {
            int idx = tid + i * 256;
            int r = idx >> 4, c = (idx & 15) << 3;
            cp16(&sm.Vs[r * VPH + c], Vp + (size_t)(t * 32 + r) * 128 + c);
        }
        cp_commit();
    };

    // Q (pre-scaled fp16) staged once, grouped with K(0)
    #pragma unroll
    for (int i = 0; i < 2; i++) {
        int idx = tid + i * 256;
        int r = idx >> 3, c = (idx & 7) << 3;
        cp16(&sm.Qs[r * QPH + c], Qp + (size_t)r * DKK + c);
    }
    loadK(0);      // commits {Q, K0}
    loadV(0);      // commits {V0}

    float accO[2][2][4];
    #pragma unroll
    for (int i = 0; i < 2; i++)
        #pragma unroll
        for (int j = 0; j < 2; j++)
            #pragma unroll
            for (int q = 0; q < 4; q++) accO[i][j][q] = 0.f;

    float rowM = -1e30f, rowL = 0.f;
    const int myrow = tid >> 2, quarter = tid & 3;
    const int lmRow = lane & 15;
    const int lmOff = (lane >> 4) << 3;

    for (int t = 0; t < 16; t++) {
        float accS[2][2][4];
        const int kb = t * 64;
        #pragma unroll
        for (int i = 0; i < 2; i++) {
            int r = wm * 32 + i * 16 + g;
            #pragma unroll
            for (int j = 0; j < 2; j++) {
                int col = kb + wn * 16 + j * 8 + t4 * 2;
                float2 b0 = *(const float2*)(Sb + (size_t)r * LL + col);
                float2 b1 = *(const float2*)(Sb + (size_t)(r + 8) * LL + col);
                accS[i][j][0] = b0.x; accS[i][j][1] = b0.y;
                accS[i][j][2] = b1.x; accS[i][j][3] = b1.y;
            }
        }

        cp_wait<1>();
        __syncthreads();

        // ---- QK^T (fp16, k=16 per step) ----
        #pragma unroll
        for (int ks = 0; ks < 4; ks++) {
            unsigned aF[2][4];
            #pragma unroll
            for (int i = 0; i < 2; i++) {
                int mb0 = wm * 32 + i * 16;
                unsigned addr = smem_u32(
                    &sm.Qs[(mb0 + lmRow) * QPH + ks * 16 + lmOff]);
                ldmatrix_x4(aF[i][0], aF[i][1], aF[i][2], aF[i][3], addr);
            }
            unsigned bF[2][2];
            #pragma unroll
            for (int j = 0; j < 2; j++) {
                int nb = wn * 16 + j * 8 + g;
                bF[j][0] = *(const unsigned*)&sm.Ks[nb * QPH + ks * 16 + t4 * 2];
                bF[j][1] = *(const unsigned*)&sm.Ks[nb * QPH + ks * 16 + t4 * 2 + 8];
            }
            #pragma unroll
            for (int i = 0; i < 2; i++)
                #pragma unroll
                for (int j = 0; j < 2; j++)
                    mma_f16(accS[i][j], aF[i], bF[j]);
        }

        // ---- scores -> Ss (fp16 row-major) ----
        #pragma unroll
        for (int i = 0; i < 2; i++) {
            int r = wm * 32 + i * 16 + g;
            #pragma unroll
            for (int j = 0; j < 2; j++) {
                int col = wn * 16 + j * 8 + t4 * 2;
                *(__half2*)&sm.Ss[r * QPH + col] =
                    __floats2half2_rn(accS[i][j][0], accS[i][j][1]);
                *(__half2*)&sm.Ss[(r + 8) * QPH + col] =
                    __floats2half2_rn(accS[i][j][2], accS[i][j][3]);
            }
        }
        __syncthreads();
        if (t + 1 < 16) loadK(t + 1);

        // ---- online softmax (fp32 math, fp16 storage) ----
        {
            float2 vals[8];
            float mx = -1e30f;
            #pragma unroll
            for (int e = 0; e < 8; e++) {
                __half2 hv = *(__half2*)&sm.Ss[myrow * QPH + quarter * 16 + e * 2];
                vals[e] = __half22float2(hv);
                mx = fmaxf(mx, fmaxf(vals[e].x, vals[e].y));
            }
            mx = fmaxf(mx, __shfl_xor_sync(0xffffffffu, mx, 1));
            mx = fmaxf(mx, __shfl_xor_sync(0xffffffffu, mx, 2));
            float mNew = fmaxf(rowM, mx);
            float scale = __expf(rowM - mNew);
            float sum = 0.f;
            #pragma unroll
            for (int e = 0; e < 8; e++) {
                vals[e].x = __expf(vals[e].x - mNew);
                vals[e].y = __expf(vals[e].y - mNew);
                sum += vals[e].x + vals[e].y;
                *(__half2*)&sm.Ss[myrow * QPH + quarter * 16 + e * 2] =
                    __floats2half2_rn(vals[e].x, vals[e].y);
            }
            sum += __shfl_xor_sync(0xffffffffu, sum, 1);
            sum += __shfl_xor_sync(0xffffffffu, sum, 2);
            rowL = rowL * scale + sum;
            rowM = mNew;
            if (quarter == 0) sm.rowScale[myrow] = scale;
        }
        if (t + 1 < 16) cp_wait<1>(); else cp_wait<0>();
        __syncthreads();

        // ---- rescale accO ----
        #pragma unroll
        for (int i = 0; i < 2; i++) {
            int r = wm * 32 + i * 16 + g;
            float s0 = sm.rowScale[r], s1 = sm.rowScale[r + 8];
            #pragma unroll
            for (int j = 0; j < 2; j++) {
                accO[i][j][0] *= s0; accO[i][j][1] *= s0;
                accO[i][j][2] *= s1; accO[i][j][3] *= s1;
            }
        }

        // ---- accO += P @ V (fp16) ----
        #pragma unroll
        for (int ks = 0; ks < 4; ks++) {
            unsigned aF[2][4];
            #pragma unroll
            for (int i = 0; i < 2; i++) {
                int mb0 = wm * 32 + i * 16;
                unsigned addr = smem_u32(
                    &sm.Ss[(mb0 + lmRow) * QPH + ks * 16 + lmOff]);
                ldmatrix_x4(aF[i][0], aF[i][1], aF[i][2], aF[i][3], addr);
            }
            unsigned bF[2][2];
            #pragma unroll
            for (int j = 0; j < 2; j++) {
                int nb = wn * 16 + j * 8 + g;
                bF[j][0] = *(const unsigned*)&sm.Vs[(ks * 8 + t4) * VPH + nb * 2];
                bF[j][1] = *(const unsigned*)&sm.Vs[(ks * 8 + t4 + 4) * VPH + nb * 2];
            }
            #pragma unroll
            for (int i = 0; i < 2; i++)
                #pragma unroll
                for (int j = 0; j < 2; j++)
                    mma_f16(accO[i][j], aF[i], bF[j]);
        }
        __syncthreads();
        if (t + 1 < 16) loadV(t + 1);
    }

    if (quarter == 0) sm.rowInv[myrow] = 1.f / rowL;
    __syncthreads();

    __half* Op = Oh + ((size_t)b * LL + q0) * DM + h * DKK;
    #pragma unroll
    for (int i = 0; i < 2; i++) {
        int r = wm * 32 + i * 16 + g;
        float i0 = sm.rowInv[r], i1 = sm.rowInv[r + 8];
        #pragma unroll
        for (int j = 0; j < 2; j++) {
            int col = wn * 16 + j * 8 + t4 * 2;
            *(__half2*)(Op + (size_t)r * DM + col) =
                __floats2half2_rn(accO[i][j][0] * i0, accO[i][j][1] * i0);
            *(__half2*)(Op + (size_t)(r + 8) * DM + col) =
                __floats2half2_rn(accO[i][j][2] * i1, accO[i][j][3] * i1);
        }
    }
}

// ---------------- layernorm (warp-shuffle), optional fp16 secondary output ----------
__global__ __launch_bounds__(256) void layernorm_kernel(
    const float* __restrict__ X, const float* __restrict__ g, const float* __restrict__ be,
    float* __restrict__ Y, __half* __restrict__ Yh)
{
    __shared__ float redS[8], redQ[8];
    const size_t row = blockIdx.x;
    const float* p = X + row * DM;
    const int tid = threadIdx.x;
    const int lane = tid & 31, w = tid >> 5;
    float v[3];
    float s = 0.f, q = 0.f;
    #pragma unroll
    for (int i = 0; i < 3; i++) {
        v[i] = p[tid + i*256];
        s += v[i];
        q = fmaf(v[i], v[i], q);
    }
    #pragma unroll
    for (int d = 16; d > 0; d >>= 1) {
        s += __shfl_xor_sync(0xffffffffu, s, d);
        q += __shfl_xor_sync(0xffffffffu, q, d);
    }
    if (lane == 0) { redS[w] = s; redQ[w] = q; }
    __syncthreads();
    {
        float s8 = redS[lane & 7], q8 = redQ[lane & 7];
        #pragma unroll
        for (int d = 4; d > 0; d >>= 1) {
            s8 += __shfl_xor_sync(0xffffffffu, s8, d);
            q8 += __shfl_xor_sync(0xffffffffu, q8, d);
        }
        s = s8; q = q8;
    }
    float mean = s * (1.f/DM);
    float var  = q * (1.f/DM) - mean * mean;
    float rstd = rsqrtf(var + 1e-5f);
    #pragma unroll
    for (int i = 0; i < 3; i++) {
        int c = tid + i*256;
        float o = (v[i] - mean) * rstd * g[c] + be[c];
        Y[row * DM + c] = o;
        if (Yh) Yh[row * DM + c] = __float2half(o);
    }
}

// ---------------- launch ----------------
extern "C" void kernel_launch(void* const* d_in, const int* in_sizes, int n_in,
                              void* d_out, int out_size)
{
    const float* src = (const float*)d_in[0];
    const float* sx  = (const float*)d_in[1];
    const float* sy  = (const float*)d_in[2];
    const float* Wq  = (const float*)d_in[3];  const float* bq  = (const float*)d_in[4];
    const float* Wk  = (const float*)d_in[5];  const float* bk  = (const float*)d_in[6];
    const float* Wv  = (const float*)d_in[7];  const float* bv  = (const float*)d_in[8];
    const float* Wo  = (const float*)d_in[9];  const float* bo  = (const float*)d_in[10];
    const float* P1  = (const float*)d_in[11]; const float* pb1 = (const float*)d_in[12];
    const float* P2  = (const float*)d_in[13]; const float* pb2 = (const float*)d_in[14];
    const float* W1  = (const float*)d_in[15]; const float* b1  = (const float*)d_in[16];
    const float* W2  = (const float*)d_in[17]; const float* b2  = (const float*)d_in[18];
    const float* g1  = (const float*)d_in[19]; const float* be1 = (const float*)d_in[20];
    const float* g2  = (const float*)d_in[21]; const float* be2 = (const float*)d_in[22];
    float* out = (float*)d_out;

    float *S, *Xres, *X1;
    __half *QH, *KH, *VH;
    __half *srcH, *WqH, *WkH, *WvH, *WoH, *W1H, *W2H, *OH, *X1H, *H1H;
    cudaGetSymbolAddress((void**)&S,    g_S);
    cudaGetSymbolAddress((void**)&Xres, g_Xres);
    cudaGetSymbolAddress((void**)&X1,   g_X1);
    cudaGetSymbolAddress((void**)&QH,   g_QH);
    cudaGetSymbolAddress((void**)&KH,   g_KH);
    cudaGetSymbolAddress((void**)&VH,   g_VH);
    cudaGetSymbolAddress((void**)&srcH, g_srcH);
    cudaGetSymbolAddress((void**)&WqH,  g_WqH);
    cudaGetSymbolAddress((void**)&WkH,  g_WkH);
    cudaGetSymbolAddress((void**)&WvH,  g_WvH);
    cudaGetSymbolAddress((void**)&WoH,  g_WoH);
    cudaGetSymbolAddress((void**)&W1H,  g_W1H);
    cudaGetSymbolAddress((void**)&W2H,  g_W2H);
    cudaGetSymbolAddress((void**)&OH,   g_OH);
    cudaGetSymbolAddress((void**)&X1H,  g_X1H);
    cudaGetSymbolAddress((void**)&H1H,  g_H1H);

    cudaFuncSetAttribute(flash64_kernel, cudaFuncAttributeMaxDynamicSharedMemorySize,
                         (int)FLH_SMEM_BYTES);
    cudaFuncSetAttribute(pbqkv_kernel, cudaFuncAttributeMaxDynamicSharedMemorySize,
                         TGH_SMEM(128, 128));
    cudaFuncSetAttribute(tgemm<1, 128, 128>, cudaFuncAttributeMaxDynamicSharedMemorySize,
                         TGH_SMEM(128, 128));
    cudaFuncSetAttribute(tgemm<2, 64, 64>, cudaFuncAttributeMaxDynamicSharedMemorySize,
                         TGH_SMEM(64, 64));

    // 0) convert src + weights to fp16 (weights k-pair-interleaved)
    prep_kernel<<<PREP_GRID, 256>>>(src, Wq, Wk, Wv, Wo, W1, W2,
                                    srcH, WqH, WkH, WvH, WoH, W1H, W2H);

    // 1) fused: relative-position bias -> S || QKV -> fp16 Q,K,V (Q/8, V interleaved)
    pbqkv_kernel<<<PBQKV_GRID, 256, TGH_SMEM(128, 128)>>>(
        srcH, WqH, bq, WkH, bk, WvH, bv, QH, KH, VH,
        sx, sy, P1, pb1, P2, pb2, S);

    // 2) flash attention (fp16 MMA): softmax(QK^T + bias) @ V -> O (fp16)
    flash64_kernel<<<dim3(LL/64, BB*NH), 256, FLH_SMEM_BYTES>>>(S, QH, KH, VH, OH);

    // 3) Xres = src + O @ Wo + bo ; LN1 -> X1 (fp32 + fp16)
    tgemm<2, 64, 64><<<dim3(DM/64, ROWS/64, 1), 256, TGH_SMEM(64, 64)>>>(
        OH, DM, WoH, DM, bo, src, Xres, DM, DM,
        nullptr, nullptr, nullptr, nullptr, nullptr, nullptr);
    layernorm_kernel<<<ROWS, 256>>>(Xres, g1, be1, X1, X1H);

    // 4) FFN: H1 = relu(X1 @ W1 + b1) (fp16) ; Xres = X1 + H1 @ W2 + b2
    tgemm<1, 128, 128><<<dim3(FFD/128, ROWS/128, 1), 256, TGH_SMEM(128, 128)>>>(
        X1H, DM, W1H, FFD, b1, nullptr, H1H, FFD, DM,
        nullptr, nullptr, nullptr, nullptr, nullptr, nullptr);
    tgemm<2, 64, 64><<<dim3(DM/64, ROWS/64, 1), 256, TGH_SMEM(64, 64)>>>(
        H1H, FFD, W2H, DM, b2, X1, Xres, DM, FFD,
        nullptr, nullptr, nullptr, nullptr, nullptr, nullptr);

    // 5) LN2 -> output
    layernorm_kernel<<<ROWS, 256>>>(Xres, g2, be2, out, nullptr);
}